// round 4
// baseline (speedup 1.0000x reference)
#include <cuda_runtime.h>
#include <cstdint>

#define BATCH 16
#define CCH   512
#define HWSZ  1024
#define NHEAD 4
#define HDIM  128
#define NGRP  32
#define CPG   16      // channels per group
#define EPSV  1e-5f

// ---------------- scratch (static device arrays; no allocations allowed) ----
__device__ float g_hn[BATCH * CCH * HWSZ];
__device__ float g_q [BATCH * CCH * HWSZ];
__device__ float g_k [BATCH * CCH * HWSZ];
__device__ float g_v [BATCH * CCH * HWSZ];
__device__ float g_ao[BATCH * CCH * HWSZ];

// ---------------- GroupNorm --------------------------------------------------
// grid = BATCH*NGRP blocks, 256 threads. Group = 16 ch x 1024 spatial = 16384 f.
__global__ __launch_bounds__(256)
void gn_kernel(const float* __restrict__ x, const float* __restrict__ gamma,
               const float* __restrict__ beta, float* __restrict__ hn)
{
    int b = blockIdx.x >> 5;
    int g = blockIdx.x & 31;
    size_t base = ((size_t)b * CCH + (size_t)g * CPG) * HWSZ;
    const float4* xb4 = (const float4*)(x + base);
    float4* hn4 = (float4*)(hn + base);
    int t = threadIdx.x;

    float s = 0.f, ss = 0.f;
    for (int i = t; i < 4096; i += 256) {
        float4 v = xb4[i];
        s  += v.x + v.y + v.z + v.w;
        ss += v.x*v.x + v.y*v.y + v.z*v.z + v.w*v.w;
    }
    // block reduce
    __shared__ float rs[8], rss[8];
    __shared__ float s_mean, s_inv;
    int lane = t & 31, wid = t >> 5;
    #pragma unroll
    for (int o = 16; o; o >>= 1) {
        s  += __shfl_xor_sync(~0u, s, o);
        ss += __shfl_xor_sync(~0u, ss, o);
    }
    if (lane == 0) { rs[wid] = s; rss[wid] = ss; }
    __syncthreads();
    if (t == 0) {
        float ts = 0.f, tss = 0.f;
        #pragma unroll
        for (int i = 0; i < 8; ++i) { ts += rs[i]; tss += rss[i]; }
        float mean = ts * (1.f / 16384.f);
        float var  = tss * (1.f / 16384.f) - mean * mean;
        s_mean = mean;
        s_inv  = rsqrtf(var + EPSV);
    }
    __syncthreads();
    float mean = s_mean, inv = s_inv;
    for (int i = t; i < 4096; i += 256) {
        int c = g * CPG + (i >> 8);       // element idx = 4i, channel = 4i/1024
        float gm = gamma[c] * inv;
        float bt = beta[c] - mean * gm;
        float4 v = xb4[i];
        v.x = v.x * gm + bt; v.y = v.y * gm + bt;
        v.z = v.z * gm + bt; v.w = v.w * gm + bt;
        hn4[i] = v;
    }
}

// ---------------- 1x1 conv GEMM ---------------------------------------------
// Out[b,o,p] = bias[o] + sum_c W[o,c]*In[b,c,p]  (+ resid[b,o,p])
// BM=BN=128, BK=16, 256 threads, 8x8 microtile.
#define GBM 128
#define GBN 128
#define GBK 16

__global__ __launch_bounds__(256)
void gemm_cpw(const float* __restrict__ W, const float* __restrict__ In,
              const float* __restrict__ bias, const float* __restrict__ resid,
              float* __restrict__ Out)
{
    __shared__ float As[GBK][132];   // transposed, padded
    __shared__ float Bs[GBK][GBN];

    int b  = blockIdx.z;
    int m0 = blockIdx.y * GBM;
    int n0 = blockIdx.x * GBN;
    size_t boff = (size_t)b * CCH * HWSZ;
    const float* Inb = In + boff;

    int t  = threadIdx.x;
    int mm = (t >> 4) * 8;
    int nn = (t & 15) * 8;

    float acc[8][8];
    #pragma unroll
    for (int i = 0; i < 8; ++i)
        #pragma unroll
        for (int j = 0; j < 8; ++j) acc[i][j] = 0.f;

    for (int k0 = 0; k0 < CCH; k0 += GBK) {
        // A tile: 128 rows(o) x 16 cols(k), store transposed
        #pragma unroll
        for (int r = 0; r < 2; ++r) {
            int f = t + r * 256;
            int row = f >> 2;
            int kq  = (f & 3) * 4;
            float4 v = *(const float4*)(W + (size_t)(m0 + row) * CCH + k0 + kq);
            As[kq + 0][row] = v.x; As[kq + 1][row] = v.y;
            As[kq + 2][row] = v.z; As[kq + 3][row] = v.w;
        }
        // B tile: 16 rows(k) x 128 cols(p)
        #pragma unroll
        for (int r = 0; r < 2; ++r) {
            int f = t + r * 256;
            int row = f >> 5;
            int col = (f & 31) * 4;
            *(float4*)(&Bs[row][col]) =
                *(const float4*)(Inb + (size_t)(k0 + row) * HWSZ + n0 + col);
        }
        __syncthreads();
        #pragma unroll
        for (int kk = 0; kk < GBK; ++kk) {
            float4 a0 = *(const float4*)(&As[kk][mm]);
            float4 a1 = *(const float4*)(&As[kk][mm + 4]);
            float4 b0 = *(const float4*)(&Bs[kk][nn]);
            float4 b1 = *(const float4*)(&Bs[kk][nn + 4]);
            float a[8] = {a0.x, a0.y, a0.z, a0.w, a1.x, a1.y, a1.z, a1.w};
            float bb[8] = {b0.x, b0.y, b0.z, b0.w, b1.x, b1.y, b1.z, b1.w};
            #pragma unroll
            for (int i = 0; i < 8; ++i)
                #pragma unroll
                for (int j = 0; j < 8; ++j) acc[i][j] += a[i] * bb[j];
        }
        __syncthreads();
    }

    // epilogue
    float* Outb = Out + boff;
    const float* Rb = resid ? (resid + boff) : nullptr;
    #pragma unroll
    for (int i = 0; i < 8; ++i) {
        int o = m0 + mm + i;
        float bv = bias[o];
        size_t row = (size_t)o * HWSZ + n0 + nn;
        #pragma unroll
        for (int j4 = 0; j4 < 2; ++j4) {
            float4 v;
            v.x = acc[i][j4 * 4 + 0] + bv;
            v.y = acc[i][j4 * 4 + 1] + bv;
            v.z = acc[i][j4 * 4 + 2] + bv;
            v.w = acc[i][j4 * 4 + 3] + bv;
            if (Rb) {
                float4 r = *(const float4*)(Rb + row + j4 * 4);
                v.x += r.x; v.y += r.y; v.z += r.z; v.w += r.w;
            }
            *(float4*)(Outb + row + j4 * 4) = v;
        }
    }
}

// ---------------- fused attention -------------------------------------------
// block = (qtile, head, batch); TQ=32 queries; full K sweep; softmax; AV.
#define TQ 32
#define SS_STRIDE 1032
#define VS_STRIDE 136
#define ATTN_SMEM ((128*TQ + TQ*SS_STRIDE + 64*VS_STRIDE + 32) * 4)

__global__ __launch_bounds__(256)
void attn_kernel(const float* __restrict__ Q, const float* __restrict__ K,
                 const float* __restrict__ V, float* __restrict__ O)
{
    extern __shared__ float smf[];
    float* Qs   = smf;                       // [128][32]
    float* Ss   = Qs + 128 * TQ;             // [32][1032]
    float* Vs   = Ss + TQ * SS_STRIDE;       // [64][136] (transposed: [kk][d])
    float* invl = Vs + 64 * VS_STRIDE;       // [32]

    int qt = blockIdx.x;                     // 0..31
    int h  = blockIdx.y;
    int b  = blockIdx.z;
    size_t base = (size_t)(b * NHEAD + h) * (HDIM * HWSZ);
    int q0 = qt * TQ;
    int t  = threadIdx.x;

    // load Q tile [128 d][32 q]
    for (int i = t; i < 128 * TQ; i += 256) {
        int d = i >> 5, qq = i & 31;
        Qs[i] = Q[base + (size_t)d * HWSZ + q0 + qq];
    }
    __syncthreads();

    const float scale = 0.08838834764831844f;  // 1/sqrt(128)

    // phase 1: S[q][k] for all 1024 k (each thread owns one k per chunk)
    for (int ch = 0; ch < 4; ++ch) {
        int kk = ch * 256 + t;
        float acc[TQ];
        #pragma unroll
        for (int i = 0; i < TQ; ++i) acc[i] = 0.f;
        const float* kp = K + base + kk;
        #pragma unroll 4
        for (int d = 0; d < 128; ++d) {
            float kv = __ldg(kp + (size_t)d * HWSZ);
            const float4* q4 = (const float4*)(Qs + d * TQ);
            #pragma unroll
            for (int qi = 0; qi < 8; ++qi) {
                float4 qv = q4[qi];
                acc[qi * 4 + 0] += qv.x * kv;
                acc[qi * 4 + 1] += qv.y * kv;
                acc[qi * 4 + 2] += qv.z * kv;
                acc[qi * 4 + 3] += qv.w * kv;
            }
        }
        #pragma unroll
        for (int qq = 0; qq < TQ; ++qq) Ss[qq * SS_STRIDE + kk] = acc[qq] * scale;
    }
    __syncthreads();

    // phase 2: softmax per row (warp per 4 rows)
    int wid = t >> 5, lane = t & 31;
    for (int rr = 0; rr < 4; ++rr) {
        int row = wid * 4 + rr;
        float* srow = Ss + row * SS_STRIDE;
        float mx = -1e30f;
        for (int i = lane; i < 1024; i += 32) mx = fmaxf(mx, srow[i]);
        #pragma unroll
        for (int o = 16; o; o >>= 1) mx = fmaxf(mx, __shfl_xor_sync(~0u, mx, o));
        float sum = 0.f;
        for (int i = lane; i < 1024; i += 32) {
            float e = __expf(srow[i] - mx);
            srow[i] = e;
            sum += e;
        }
        #pragma unroll
        for (int o = 16; o; o >>= 1) sum += __shfl_xor_sync(~0u, sum, o);
        if (lane == 0) invl[row] = 1.f / sum;
    }
    __syncthreads();

    // phase 3: O[d][q] = sum_k P[q][k] V[d][k]; thread = 4d x 4q microtile
    int d0 = (t & 31) * 4;
    int qg = (t >> 5) * 4;
    float acc[4][4];   // [qi][di]
    #pragma unroll
    for (int i = 0; i < 4; ++i)
        #pragma unroll
        for (int j = 0; j < 4; ++j) acc[i][j] = 0.f;

    for (int kt = 0; kt < 1024; kt += 64) {
        // load V tile transposed: Vs[kk][d]
        for (int i = t; i < 64 * 128; i += 256) {
            int d = i >> 6, kk2 = i & 63;
            Vs[kk2 * VS_STRIDE + d] = V[base + (size_t)d * HWSZ + kt + kk2];
        }
        __syncthreads();
        for (int kk = 0; kk < 64; kk += 4) {
            float p[16];
            #pragma unroll
            for (int qi = 0; qi < 4; ++qi)
                *(float4*)(p + qi * 4) =
                    *(const float4*)(Ss + (qg + qi) * SS_STRIDE + kt + kk);
            #pragma unroll
            for (int u = 0; u < 4; ++u) {
                float4 vv = *(const float4*)(Vs + (kk + u) * VS_STRIDE + d0);
                #pragma unroll
                for (int qi = 0; qi < 4; ++qi) {
                    float pv = p[qi * 4 + u];
                    acc[qi][0] += pv * vv.x;
                    acc[qi][1] += pv * vv.y;
                    acc[qi][2] += pv * vv.z;
                    acc[qi][3] += pv * vv.w;
                }
            }
        }
        __syncthreads();
    }

    #pragma unroll
    for (int qi = 0; qi < 4; ++qi) {
        float il = invl[qg + qi];
        #pragma unroll
        for (int di = 0; di < 4; ++di)
            O[base + (size_t)(d0 + di) * HWSZ + q0 + qg + qi] = acc[qi][di] * il;
    }
}

// ---------------- launch ------------------------------------------------------
extern "C" void kernel_launch(void* const* d_in, const int* in_sizes, int n_in,
                              void* d_out, int out_size)
{
    const float* x     = (const float*)d_in[0];
    const float* gamma = (const float*)d_in[1];
    const float* beta  = (const float*)d_in[2];
    const float* wq    = (const float*)d_in[3];
    const float* bq    = (const float*)d_in[4];
    const float* wk    = (const float*)d_in[5];
    const float* bk    = (const float*)d_in[6];
    const float* wv    = (const float*)d_in[7];
    const float* bv    = (const float*)d_in[8];
    const float* wp    = (const float*)d_in[9];
    const float* bp    = (const float*)d_in[10];
    float* out = (float*)d_out;

    float *hn, *q, *k, *v, *ao;
    cudaGetSymbolAddress((void**)&hn, g_hn);
    cudaGetSymbolAddress((void**)&q,  g_q);
    cudaGetSymbolAddress((void**)&k,  g_k);
    cudaGetSymbolAddress((void**)&v,  g_v);
    cudaGetSymbolAddress((void**)&ao, g_ao);

    cudaFuncSetAttribute(attn_kernel, cudaFuncAttributeMaxDynamicSharedMemorySize,
                         ATTN_SMEM);

    gn_kernel<<<BATCH * NGRP, 256>>>(x, gamma, beta, hn);

    dim3 gg(HWSZ / GBN, CCH / GBM, BATCH);   // (8, 4, 16)
    gemm_cpw<<<gg, 256>>>(wq, hn, bq, nullptr, q);
    gemm_cpw<<<gg, 256>>>(wk, hn, bk, nullptr, k);
    gemm_cpw<<<gg, 256>>>(wv, hn, bv, nullptr, v);

    attn_kernel<<<dim3(HWSZ / TQ, NHEAD, BATCH), 256, ATTN_SMEM>>>(q, k, v, ao);

    gemm_cpw<<<gg, 256>>>(wp, ao, bp, x, out);
}

// round 7
// speedup vs baseline: 3.7782x; 3.7782x over previous
#include <cuda_runtime.h>
#include <cuda_bf16.h>
#include <cstdint>

using bf16 = __nv_bfloat16;

#define BATCH 16
#define CCH   512
#define HWSZ  1024
#define NHEAD 4
#define HDIM  128
#define NGRP  32
#define CPG   16
#define EPSV  1e-5f

// ======================= PTX helpers ========================================
__device__ __forceinline__ uint32_t smem_to_u32(const void* p) {
    uint32_t a;
    asm("{ .reg .u64 t; cvta.to.shared.u64 t, %1; cvt.u32.u64 %0, t; }"
        : "=r"(a) : "l"(p));
    return a;
}
__device__ __forceinline__ void cp16(uint32_t dst, const void* src) {
    asm volatile("cp.async.cg.shared.global [%0], [%1], 16;"
                 :: "r"(dst), "l"(src));
}
#define CP_COMMIT() asm volatile("cp.async.commit_group;" ::: "memory")
#define CP_WAIT(n)  asm volatile("cp.async.wait_group %0;" :: "n"(n) : "memory")

__device__ __forceinline__ void ldsm4(uint32_t* r, uint32_t addr) {
    asm volatile("ldmatrix.sync.aligned.m8n8.x4.shared.b16 {%0,%1,%2,%3}, [%4];"
                 : "=r"(r[0]), "=r"(r[1]), "=r"(r[2]), "=r"(r[3]) : "r"(addr));
}
__device__ __forceinline__ void mma16816(float* c, const uint32_t* a,
                                         uint32_t b0, uint32_t b1) {
    asm volatile(
        "mma.sync.aligned.m16n8k16.row.col.f32.bf16.bf16.f32 "
        "{%0,%1,%2,%3}, {%4,%5,%6,%7}, {%8,%9}, {%0,%1,%2,%3};"
        : "+f"(c[0]), "+f"(c[1]), "+f"(c[2]), "+f"(c[3])
        : "r"(a[0]), "r"(a[1]), "r"(a[2]), "r"(a[3]), "r"(b0), "r"(b1));
}
__device__ __forceinline__ void split_bf16(float v, bf16& h, bf16& l) {
    h = __float2bfloat16(v);
    l = __float2bfloat16(v - __bfloat162float(h));
}

// ========================= scratch (static) ================================
__device__ float g_hn   [BATCH * CCH * HWSZ];            // GN out fp32 [b][c][p]
__device__ bf16  g_hnT_h[BATCH * HWSZ * CCH];            // [b][p][c]
__device__ bf16  g_hnT_l[BATCH * HWSZ * CCH];
__device__ bf16  g_w_h  [4 * CCH * CCH];                 // wq,wk,wv,wp [o][c]
__device__ bf16  g_w_l  [4 * CCH * CCH];
__device__ bf16  g_qT_h [BATCH * NHEAD * HWSZ * HDIM];   // [bh][p][d]
__device__ bf16  g_qT_l [BATCH * NHEAD * HWSZ * HDIM];
__device__ bf16  g_kT_h [BATCH * NHEAD * HWSZ * HDIM];
__device__ bf16  g_kT_l [BATCH * NHEAD * HWSZ * HDIM];
__device__ bf16  g_v_h  [BATCH * NHEAD * HDIM * HWSZ];   // [bh][d][p]
__device__ bf16  g_v_l  [BATCH * NHEAD * HDIM * HWSZ];
__device__ float g_S    [(size_t)64 * HWSZ * HWSZ];      // [bh][q][k]
__device__ bf16  g_P_h  [(size_t)64 * HWSZ * HWSZ];      // [bh][q][k]
__device__ bf16  g_P_l  [(size_t)64 * HWSZ * HWSZ];
__device__ bf16  g_aoT_h[BATCH * HWSZ * CCH];            // [b][p][c]
__device__ bf16  g_aoT_l[BATCH * HWSZ * CCH];

// ========================= GroupNorm =======================================
__global__ __launch_bounds__(256)
void gn_kernel(const float* __restrict__ x, const float* __restrict__ gamma,
               const float* __restrict__ beta, float* __restrict__ hn)
{
    int b = blockIdx.x >> 5;
    int g = blockIdx.x & 31;
    size_t base = ((size_t)b * CCH + (size_t)g * CPG) * HWSZ;
    const float4* xb4 = (const float4*)(x + base);
    float4* hn4 = (float4*)(hn + base);
    int t = threadIdx.x;

    float s = 0.f, ss = 0.f;
    for (int i = t; i < 4096; i += 256) {
        float4 v = xb4[i];
        s  += v.x + v.y + v.z + v.w;
        ss += v.x*v.x + v.y*v.y + v.z*v.z + v.w*v.w;
    }
    __shared__ float rs[8], rss[8];
    __shared__ float s_mean, s_inv;
    int lane = t & 31, wid = t >> 5;
    #pragma unroll
    for (int o = 16; o; o >>= 1) {
        s  += __shfl_xor_sync(~0u, s, o);
        ss += __shfl_xor_sync(~0u, ss, o);
    }
    if (lane == 0) { rs[wid] = s; rss[wid] = ss; }
    __syncthreads();
    if (t == 0) {
        float ts = 0.f, tss = 0.f;
        #pragma unroll
        for (int i = 0; i < 8; ++i) { ts += rs[i]; tss += rss[i]; }
        float mean = ts * (1.f / 16384.f);
        float var  = tss * (1.f / 16384.f) - mean * mean;
        s_mean = mean;
        s_inv  = rsqrtf(var + EPSV);
    }
    __syncthreads();
    float mean = s_mean, inv = s_inv;
    for (int i = t; i < 4096; i += 256) {
        int c = g * CPG + (i >> 8);
        float gm = gamma[c] * inv;
        float bt = beta[c] - mean * gm;
        float4 v = xb4[i];
        v.x = v.x * gm + bt; v.y = v.y * gm + bt;
        v.z = v.z * gm + bt; v.w = v.w * gm + bt;
        hn4[i] = v;
    }
}

// ==================== transpose + bf16 split: hn -> hnT ====================
__global__ __launch_bounds__(256)
void tsplit_kernel(const float* __restrict__ hn,
                   bf16* __restrict__ Th, bf16* __restrict__ Tl)
{
    __shared__ float tl[32][33];
    int p0 = blockIdx.x * 32, c0 = blockIdx.y * 32, b = blockIdx.z;
    int tx = threadIdx.x, ty = threadIdx.y;
    #pragma unroll
    for (int j = 0; j < 4; ++j)
        tl[ty + 8*j][tx] = hn[((size_t)b*CCH + c0 + ty + 8*j) * HWSZ + p0 + tx];
    __syncthreads();
    #pragma unroll
    for (int j = 0; j < 4; ++j) {
        float v = tl[tx][ty + 8*j];
        bf16 h, l; split_bf16(v, h, l);
        size_t o = ((size_t)b*HWSZ + p0 + ty + 8*j) * CCH + c0 + tx;
        Th[o] = h; Tl[o] = l;
    }
}

// ==================== weight bf16 split =====================================
__global__ __launch_bounds__(256)
void wsplit_kernel(const float* __restrict__ W0, const float* __restrict__ W1,
                   const float* __restrict__ W2, const float* __restrict__ W3,
                   bf16* __restrict__ Wh, bf16* __restrict__ Wl)
{
    const float* W = blockIdx.y == 0 ? W0 : blockIdx.y == 1 ? W1 :
                     blockIdx.y == 2 ? W2 : W3;
    size_t i = (size_t)blockIdx.x * 256 + threadIdx.x;
    bf16 h, l; split_bf16(W[i], h, l);
    size_t o = (size_t)blockIdx.y * (CCH * CCH) + i;
    Wh[o] = h; Wl[o] = l;
}

// ==================== unified HMMA GEMM ====================================
// D[128 m][128 n] = sum_K (Ah+Al)[m][K] * (Bh+Bl)[n][K]   (3-term split)
// BK=32. A,B both K-major (row-major with k contiguous). 8 warps: 4(M)x2(N),
// warp tile 32x64, mma.m16n8k16 row.col, ldmatrix non-trans for both.
//
// smem tile: 128 rows x 40 bf16 (80B stride, conflict-free ldmatrix).
// Epilogue stages acc in smem [128][132] fp32, then coalesced global writes.
//
// Modes:
//  0: q/k conv — M=p, N=o(head*128+d); +bias[n]; bf16 h/l out [bh][p][d]
//  1: v conv   — M=o, N=p; +bias[m]; bf16 h/l out [bh][d][p]
//  2: S        — M=q, N=k; *scale; fp32 out [z][q][k]
//  3: AV       — M=q, N=d; bf16 h/l out aoT [b][p][head*128+d]
//  4: proj     — M=p, N=o; +bias[n]+resid; fp32 out [b][o][p] (transposed st)
#define TILE_B   10240              // 128*80
#define BUF_B    (4 * TILE_B)       // Ah, Al, Bh, Bl
#define SMEM_GEMM (2 * BUF_B)       // 81920

__device__ __forceinline__ void load_chunk_hmma(
    const bf16* __restrict__ Ahb, const bf16* __restrict__ Alb,
    const bf16* __restrict__ Bhb, const bf16* __restrict__ Blb,
    int K, int m0, int n0, int kc, uint32_t bufb, int t)
{
    #pragma unroll
    for (int it = 0; it < 2; ++it) {
        int idx = t + it * 256;          // 0..511
        int r   = idx >> 2;              // row 0..127
        int sg  = (idx & 3) * 16;        // 16B segment in 64B row
        uint32_t so = (uint32_t)r * 80 + sg;
        cp16(bufb + so,
             (const char*)(Ahb + (size_t)(m0 + r) * K + kc) + sg);
        cp16(bufb + TILE_B + so,
             (const char*)(Alb + (size_t)(m0 + r) * K + kc) + sg);
        cp16(bufb + 2 * TILE_B + so,
             (const char*)(Bhb + (size_t)(n0 + r) * K + kc) + sg);
        cp16(bufb + 3 * TILE_B + so,
             (const char*)(Blb + (size_t)(n0 + r) * K + kc) + sg);
    }
}

template <int MODE>
__global__ __launch_bounds__(256)
void gemm_hmma(const bf16* __restrict__ Ah, const bf16* __restrict__ Al, long long A_bs,
               const bf16* __restrict__ Bh, const bf16* __restrict__ Bl, long long B_bs,
               int K, const float* __restrict__ bias, const float* __restrict__ resid,
               bf16* __restrict__ Oh, bf16* __restrict__ Ol, float* __restrict__ Of)
{
    extern __shared__ char smem[];
    uint32_t sbase = smem_to_u32(smem);
    int t = threadIdx.x;
    int wid = t >> 5, lane = t & 31;
    int m0 = blockIdx.y * 128, n0 = blockIdx.x * 128, z = blockIdx.z;

    const bf16* Ahb = Ah + (long long)z * A_bs;
    const bf16* Alb = Al + (long long)z * A_bs;
    const bf16* Bhb = Bh + (long long)z * B_bs;
    const bf16* Blb = Bl + (long long)z * B_bs;

    int wm = wid & 3;       // 0..3 : M offset wm*32
    int wn = wid >> 2;      // 0..1 : N offset wn*64

    // ldmatrix base offsets (within a tile, relative to buffer base)
    uint32_t aOff = (uint32_t)(wm * 32 + (lane & 15)) * 80 + (lane >> 4) * 16;
    uint32_t bOff = (uint32_t)(wn * 64 + (lane & 15)) * 80 + (lane >> 4) * 16;

    float acc[2][8][4];
    #pragma unroll
    for (int i = 0; i < 2; ++i)
        #pragma unroll
        for (int j = 0; j < 8; ++j)
            #pragma unroll
            for (int c = 0; c < 4; ++c) acc[i][j][c] = 0.f;

    const int NC = K >> 5;

    load_chunk_hmma(Ahb, Alb, Bhb, Blb, K, m0, n0, 0, sbase, t);
    CP_COMMIT();

    for (int i = 0; i < NC; ++i) {
        if (i + 1 < NC) {
            load_chunk_hmma(Ahb, Alb, Bhb, Blb, K, m0, n0, (i + 1) * 32,
                            sbase + ((i + 1) & 1) * BUF_B, t);
            CP_COMMIT();
            CP_WAIT(1);
        } else {
            CP_WAIT(0);
        }
        __syncthreads();

        uint32_t base = sbase + (i & 1) * BUF_B;
        #pragma unroll
        for (int kst = 0; kst < 2; ++kst) {
            uint32_t ko = kst * 32;
            uint32_t ah[2][4], al[2][4];
            #pragma unroll
            for (int mt = 0; mt < 2; ++mt) {
                uint32_t ad = base + aOff + mt * (16 * 80) + ko;
                ldsm4(ah[mt], ad);
                ldsm4(al[mt], ad + TILE_B);
            }
            #pragma unroll
            for (int np = 0; np < 4; ++np) {
                uint32_t bd = base + bOff + np * (16 * 80) + ko + 2 * TILE_B;
                uint32_t bh[4], bl[4];
                ldsm4(bh, bd);
                ldsm4(bl, bd + TILE_B);
                #pragma unroll
                for (int o = 0; o < 2; ++o) {
                    int nt = np * 2 + o;
                    #pragma unroll
                    for (int mt = 0; mt < 2; ++mt) {
                        mma16816(acc[mt][nt], ah[mt], bh[o], bh[2 + o]);
                        mma16816(acc[mt][nt], ah[mt], bl[o], bl[2 + o]);
                        mma16816(acc[mt][nt], al[mt], bh[o], bh[2 + o]);
                    }
                }
            }
        }
        __syncthreads();
    }

    // ---- epilogue: stage acc into smem fp32 [128][132] ----
    float* st = (float*)smem;
    #pragma unroll
    for (int mt = 0; mt < 2; ++mt) {
        int r = wm * 32 + mt * 16 + (lane >> 2);
        #pragma unroll
        for (int nt = 0; nt < 8; ++nt) {
            int c = wn * 64 + nt * 8 + (lane & 3) * 2;
            const float* a = acc[mt][nt];
            if (MODE == 4) {  // transposed staging: st[n][m]
                st[(c    ) * 132 + r    ] = a[0];
                st[(c + 1) * 132 + r    ] = a[1];
                st[(c    ) * 132 + r + 8] = a[2];
                st[(c + 1) * 132 + r + 8] = a[3];
            } else {          // st[m][n]
                st[(r    ) * 132 + c    ] = a[0];
                st[(r    ) * 132 + c + 1] = a[1];
                st[(r + 8) * 132 + c    ] = a[2];
                st[(r + 8) * 132 + c + 1] = a[3];
            }
        }
    }
    __syncthreads();

    if (MODE == 2) {
        const float scale = 0.08838834764831844f;  // 1/sqrt(128)
        for (int idx = t; idx < 4096; idx += 256) {
            int m = idx >> 5, c4 = (idx & 31) * 4;
            float4 v = *(const float4*)(st + m * 132 + c4);
            v.x *= scale; v.y *= scale; v.z *= scale; v.w *= scale;
            *(float4*)(Of + (size_t)z * 1048576 + (size_t)(m0 + m) * 1024
                       + n0 + c4) = v;
        }
    } else if (MODE == 4) {
        for (int idx = t; idx < 4096; idx += 256) {
            int n = idx >> 5, m4 = (idx & 31) * 4;
            size_t a = (size_t)z * 524288 + (size_t)(n0 + n) * 1024 + m0 + m4;
            float bv = __ldg(bias + n0 + n);
            float4 v = *(const float4*)(st + n * 132 + m4);
            float4 rr = *(const float4*)(resid + a);
            v.x += bv + rr.x; v.y += bv + rr.y;
            v.z += bv + rr.z; v.w += bv + rr.w;
            *(float4*)(Of + a) = v;
        }
    } else {
        for (int idx = t; idx < 8192; idx += 256) {
            int m = idx >> 6, cp = (idx & 63) * 2;
            float v0 = st[m * 132 + cp];
            float v1 = st[m * 132 + cp + 1];
            size_t off;
            if (MODE == 0) {
                v0 += __ldg(bias + n0 + cp);
                v1 += __ldg(bias + n0 + cp + 1);
                off = (size_t)z * 524288 + (size_t)n0 * 1024
                    + (size_t)(m0 + m) * 128 + cp;
            } else if (MODE == 1) {
                float bv = __ldg(bias + m0 + m);
                v0 += bv; v1 += bv;
                off = (size_t)z * 524288 + (size_t)(m0 + m) * 1024 + n0 + cp;
            } else { // MODE 3
                off = (size_t)(z >> 2) * 524288 + (size_t)(m0 + m) * 512
                    + (size_t)(z & 3) * 128 + cp;
            }
            bf16 h0, l0, h1, l1;
            split_bf16(v0, h0, l0);
            split_bf16(v1, h1, l1);
            *(__nv_bfloat162*)(Oh + off) = __halves2bfloat162(h0, h1);
            *(__nv_bfloat162*)(Ol + off) = __halves2bfloat162(l0, l1);
        }
    }
}

// ==================== softmax: S -> P (bf16 hi/lo) =========================
__global__ __launch_bounds__(256)
void softmax_kernel(const float* __restrict__ S,
                    bf16* __restrict__ Ph, bf16* __restrict__ Pl)
{
    size_t row = (size_t)blockIdx.x * 8 + (threadIdx.x >> 5);
    int lane = threadIdx.x & 31;
    const float4* src = (const float4*)(S + row * 1024);
    float4 v[8];
    float m = -1e30f;
    #pragma unroll
    for (int j = 0; j < 8; ++j) {
        v[j] = src[j * 32 + lane];
        m = fmaxf(m, fmaxf(fmaxf(v[j].x, v[j].y), fmaxf(v[j].z, v[j].w)));
    }
    #pragma unroll
    for (int o = 16; o; o >>= 1) m = fmaxf(m, __shfl_xor_sync(~0u, m, o));
    float s = 0.f;
    #pragma unroll
    for (int j = 0; j < 8; ++j) {
        v[j].x = __expf(v[j].x - m); v[j].y = __expf(v[j].y - m);
        v[j].z = __expf(v[j].z - m); v[j].w = __expf(v[j].w - m);
        s += v[j].x + v[j].y + v[j].z + v[j].w;
    }
    #pragma unroll
    for (int o = 16; o; o >>= 1) s += __shfl_xor_sync(~0u, s, o);
    float inv = 1.f / s;
    #pragma unroll
    for (int j = 0; j < 8; ++j) {
        float p[4] = {v[j].x * inv, v[j].y * inv, v[j].z * inv, v[j].w * inv};
        bf16 h[4], l[4];
        #pragma unroll
        for (int c = 0; c < 4; ++c) split_bf16(p[c], h[c], l[c]);
        size_t o4 = row * 1024 + (size_t)(j * 32 + lane) * 4;
        *(__nv_bfloat162*)(Ph + o4)     = __halves2bfloat162(h[0], h[1]);
        *(__nv_bfloat162*)(Ph + o4 + 2) = __halves2bfloat162(h[2], h[3]);
        *(__nv_bfloat162*)(Pl + o4)     = __halves2bfloat162(l[0], l[1]);
        *(__nv_bfloat162*)(Pl + o4 + 2) = __halves2bfloat162(l[2], l[3]);
    }
}

// ==================== launch ================================================
extern "C" void kernel_launch(void* const* d_in, const int* in_sizes, int n_in,
                              void* d_out, int out_size)
{
    const float* x     = (const float*)d_in[0];
    const float* gamma = (const float*)d_in[1];
    const float* beta  = (const float*)d_in[2];
    const float* wq    = (const float*)d_in[3];
    const float* bq    = (const float*)d_in[4];
    const float* wk    = (const float*)d_in[5];
    const float* bk    = (const float*)d_in[6];
    const float* wv    = (const float*)d_in[7];
    const float* bv    = (const float*)d_in[8];
    const float* wp    = (const float*)d_in[9];
    const float* bp    = (const float*)d_in[10];
    float* out = (float*)d_out;

    float *hn, *S;
    bf16 *hnTh, *hnTl, *Wh, *Wl, *qTh, *qTl, *kTh, *kTl, *vh, *vl, *Psh, *Psl, *aoh, *aol;
    cudaGetSymbolAddress((void**)&hn,   g_hn);
    cudaGetSymbolAddress((void**)&hnTh, g_hnT_h);
    cudaGetSymbolAddress((void**)&hnTl, g_hnT_l);
    cudaGetSymbolAddress((void**)&Wh,   g_w_h);
    cudaGetSymbolAddress((void**)&Wl,   g_w_l);
    cudaGetSymbolAddress((void**)&qTh,  g_qT_h);
    cudaGetSymbolAddress((void**)&qTl,  g_qT_l);
    cudaGetSymbolAddress((void**)&kTh,  g_kT_h);
    cudaGetSymbolAddress((void**)&kTl,  g_kT_l);
    cudaGetSymbolAddress((void**)&vh,   g_v_h);
    cudaGetSymbolAddress((void**)&vl,   g_v_l);
    cudaGetSymbolAddress((void**)&S,    g_S);
    cudaGetSymbolAddress((void**)&Psh,  g_P_h);
    cudaGetSymbolAddress((void**)&Psl,  g_P_l);
    cudaGetSymbolAddress((void**)&aoh,  g_aoT_h);
    cudaGetSymbolAddress((void**)&aol,  g_aoT_l);

    cudaFuncSetAttribute(gemm_hmma<0>, cudaFuncAttributeMaxDynamicSharedMemorySize, SMEM_GEMM);
    cudaFuncSetAttribute(gemm_hmma<1>, cudaFuncAttributeMaxDynamicSharedMemorySize, SMEM_GEMM);
    cudaFuncSetAttribute(gemm_hmma<2>, cudaFuncAttributeMaxDynamicSharedMemorySize, SMEM_GEMM);
    cudaFuncSetAttribute(gemm_hmma<3>, cudaFuncAttributeMaxDynamicSharedMemorySize, SMEM_GEMM);
    cudaFuncSetAttribute(gemm_hmma<4>, cudaFuncAttributeMaxDynamicSharedMemorySize, SMEM_GEMM);

    gn_kernel<<<BATCH * NGRP, 256>>>(x, gamma, beta, hn);
    tsplit_kernel<<<dim3(32, 16, BATCH), dim3(32, 8)>>>(hn, hnTh, hnTl);
    wsplit_kernel<<<dim3(1024, 4), 256>>>(wq, wk, wv, wp, Wh, Wl);

    const long long HNB = (long long)HWSZ * CCH;     // 524288
    const long long QKB = (long long)HWSZ * HDIM;    // 131072
    const long long WS  = (long long)CCH * CCH;      // 262144

    // Q, K: D[p][o] — A = hnT (M=p), B = W (N=o)
    gemm_hmma<0><<<dim3(4, 8, BATCH), 256, SMEM_GEMM>>>(
        hnTh, hnTl, HNB, Wh + 0 * WS, Wl + 0 * WS, 0, CCH, bq, nullptr, qTh, qTl, nullptr);
    gemm_hmma<0><<<dim3(4, 8, BATCH), 256, SMEM_GEMM>>>(
        hnTh, hnTl, HNB, Wh + 1 * WS, Wl + 1 * WS, 0, CCH, bk, nullptr, kTh, kTl, nullptr);
    // V: D[o][p] — A = W (M=o), B = hnT (N=p)
    gemm_hmma<1><<<dim3(8, 4, BATCH), 256, SMEM_GEMM>>>(
        Wh + 2 * WS, Wl + 2 * WS, 0, hnTh, hnTl, HNB, CCH, bv, nullptr, vh, vl, nullptr);
    // S = Q·K^T * scale, stored [z][q][k]
    gemm_hmma<2><<<dim3(8, 8, 64), 256, SMEM_GEMM>>>(
        qTh, qTl, QKB, kTh, kTl, QKB, HDIM, nullptr, nullptr, nullptr, nullptr, S);
    // softmax rows (z,q) over k
    softmax_kernel<<<8192, 256>>>(S, Psh, Psl);
    // O = P·V^T : D[q][d] -> aoT [b][p][c]
    gemm_hmma<3><<<dim3(1, 8, 64), 256, SMEM_GEMM>>>(
        Psh, Psl, (long long)HWSZ * HWSZ, vh, vl, QKB, HWSZ,
        nullptr, nullptr, aoh, aol, nullptr);
    // proj + bias + residual -> out [b][o][p]
    gemm_hmma<4><<<dim3(4, 8, BATCH), 256, SMEM_GEMM>>>(
        aoh, aol, HNB, Wh + 3 * WS, Wl + 3 * WS, 0, CCH, bp, x, nullptr, nullptr, out);
}

// round 8
// speedup vs baseline: 5.4920x; 1.4536x over previous
#include <cuda_runtime.h>
#include <cuda_bf16.h>
#include <cstdint>

#define BATCH 16
#define CCH   512
#define HWSZ  1024
#define NHEAD 4
#define HDIM  128
#define NGRP  32
#define CPG   16
#define EPSV  1e-5f

// ======================= PTX helpers ========================================
__device__ __forceinline__ uint32_t smem_to_u32(const void* p) {
    uint32_t a;
    asm("{ .reg .u64 t; cvta.to.shared.u64 t, %1; cvt.u32.u64 %0, t; }"
        : "=r"(a) : "l"(p));
    return a;
}
__device__ __forceinline__ void cp16(uint32_t dst, const void* src) {
    asm volatile("cp.async.cg.shared.global [%0], [%1], 16;"
                 :: "r"(dst), "l"(src));
}
#define CP_COMMIT() asm volatile("cp.async.commit_group;" ::: "memory")
#define CP_WAIT(n)  asm volatile("cp.async.wait_group %0;" :: "n"(n) : "memory")

__device__ __forceinline__ void ldsm4(uint32_t* r, uint32_t addr) {
    asm volatile("ldmatrix.sync.aligned.m8n8.x4.shared.b16 {%0,%1,%2,%3}, [%4];"
                 : "=r"(r[0]), "=r"(r[1]), "=r"(r[2]), "=r"(r[3]) : "r"(addr));
}
__device__ __forceinline__ void mma_tf32(float* c, const uint32_t* a,
                                         uint32_t b0, uint32_t b1) {
    asm volatile(
        "mma.sync.aligned.m16n8k8.row.col.f32.tf32.tf32.f32 "
        "{%0,%1,%2,%3}, {%4,%5,%6,%7}, {%8,%9}, {%0,%1,%2,%3};"
        : "+f"(c[0]), "+f"(c[1]), "+f"(c[2]), "+f"(c[3])
        : "r"(a[0]), "r"(a[1]), "r"(a[2]), "r"(a[3]), "r"(b0), "r"(b1));
}
__device__ __forceinline__ float to_tf32(float x) {
    uint32_t u;
    asm("cvt.rna.tf32.f32 %0, %1;" : "=r"(u) : "f"(x));
    return __uint_as_float(u);
}

// ========================= scratch (static) ================================
__device__ float g_hn [BATCH * CCH * HWSZ];            // GN out [b][c][p]
__device__ float g_hnT[BATCH * HWSZ * CCH];            // tf32-rounded [b][p][c]
__device__ float g_w  [4 * CCH * CCH];                 // tf32 wq,wk,wv,wp [o][c]
__device__ float g_q  [BATCH * NHEAD * HWSZ * HDIM];   // [bh][p][d]
__device__ float g_k  [BATCH * NHEAD * HWSZ * HDIM];   // [bh][p][d]
__device__ float g_v  [BATCH * NHEAD * HDIM * HWSZ];   // [bh][d][p]
__device__ float g_S  [(size_t)64 * HWSZ * HWSZ];      // [bh][q][k]
__device__ float g_P  [(size_t)64 * HWSZ * HWSZ];      // tf32 [bh][q][k]
__device__ float g_ao [BATCH * HWSZ * CCH];            // tf32 [b][p][c]

// ========================= GroupNorm =======================================
__global__ __launch_bounds__(256)
void gn_kernel(const float* __restrict__ x, const float* __restrict__ gamma,
               const float* __restrict__ beta, float* __restrict__ hn)
{
    int b = blockIdx.x >> 5;
    int g = blockIdx.x & 31;
    size_t base = ((size_t)b * CCH + (size_t)g * CPG) * HWSZ;
    const float4* xb4 = (const float4*)(x + base);
    float4* hn4 = (float4*)(hn + base);
    int t = threadIdx.x;

    float s = 0.f, ss = 0.f;
    for (int i = t; i < 4096; i += 256) {
        float4 v = xb4[i];
        s  += v.x + v.y + v.z + v.w;
        ss += v.x*v.x + v.y*v.y + v.z*v.z + v.w*v.w;
    }
    __shared__ float rs[8], rss[8];
    __shared__ float s_mean, s_inv;
    int lane = t & 31, wid = t >> 5;
    #pragma unroll
    for (int o = 16; o; o >>= 1) {
        s  += __shfl_xor_sync(~0u, s, o);
        ss += __shfl_xor_sync(~0u, ss, o);
    }
    if (lane == 0) { rs[wid] = s; rss[wid] = ss; }
    __syncthreads();
    if (t == 0) {
        float ts = 0.f, tss = 0.f;
        #pragma unroll
        for (int i = 0; i < 8; ++i) { ts += rs[i]; tss += rss[i]; }
        float mean = ts * (1.f / 16384.f);
        float var  = tss * (1.f / 16384.f) - mean * mean;
        s_mean = mean;
        s_inv  = rsqrtf(var + EPSV);
    }
    __syncthreads();
    float mean = s_mean, inv = s_inv;
    for (int i = t; i < 4096; i += 256) {
        int c = g * CPG + (i >> 8);
        float gm = gamma[c] * inv;
        float bt = beta[c] - mean * gm;
        float4 v = xb4[i];
        v.x = v.x * gm + bt; v.y = v.y * gm + bt;
        v.z = v.z * gm + bt; v.w = v.w * gm + bt;
        hn4[i] = v;
    }
}

// ==================== transpose + tf32 round: hn -> hnT ====================
__global__ __launch_bounds__(256)
void t_tf32_kernel(const float* __restrict__ hn, float* __restrict__ T)
{
    __shared__ float tl[32][33];
    int p0 = blockIdx.x * 32, c0 = blockIdx.y * 32, b = blockIdx.z;
    int tx = threadIdx.x, ty = threadIdx.y;
    #pragma unroll
    for (int j = 0; j < 4; ++j)
        tl[ty + 8*j][tx] = hn[((size_t)b*CCH + c0 + ty + 8*j) * HWSZ + p0 + tx];
    __syncthreads();
    #pragma unroll
    for (int j = 0; j < 4; ++j) {
        size_t o = ((size_t)b*HWSZ + p0 + ty + 8*j) * CCH + c0 + tx;
        T[o] = to_tf32(tl[tx][ty + 8*j]);
    }
}

// ==================== weight tf32 round =====================================
__global__ __launch_bounds__(256)
void wconv_kernel(const float* __restrict__ W0, const float* __restrict__ W1,
                  const float* __restrict__ W2, const float* __restrict__ W3,
                  float* __restrict__ Wo)
{
    const float* W = blockIdx.y == 0 ? W0 : blockIdx.y == 1 ? W1 :
                     blockIdx.y == 2 ? W2 : W3;
    size_t i = (size_t)blockIdx.x * 256 + threadIdx.x;
    Wo[(size_t)blockIdx.y * (CCH * CCH) + i] = to_tf32(W[i]);
}

// ==================== unified TF32 HMMA GEMM ===============================
// D[128 m][128 n] = sum_K A[m][K] * B[n][K]   (single-pass tf32)
// BK=32. A,B K-major fp32 (tf32-rounded by producers). 8 warps 4(M)x2(N),
// warp tile 32x64, mma.m16n8k8.tf32, ldsm on 144B-stride rows (conflict-free).
//
// Modes:
//  0: q/k conv — M=p, N=o; +bias[n]; tf32 out [bh][p][d]
//  1: v conv   — M=o, N=p; +bias[m]; tf32 out [bh][d][p]
//  2: S        — M=q, N=k; raw fp32 out [z][q][k]
//  3: AV       — M=q, N=d; tf32 out ao [b][p][head*128+d]
//  4: proj     — M=p, N=o; +bias[n]+resid; fp32 out [b][o][p] (transposed st)
#define TSTRIDE  144                 // 32 fp32 = 128B + 16B pad
#define TILE_T   18432               // 128 * 144
#define STAGE_T  (2 * TILE_T)        // A + B
#define SMEM_GEMM (2 * STAGE_T)      // 73728 (also covers 128x132 f32 epilogue)

__device__ __forceinline__ void load_chunk_t(
    const float* __restrict__ Ab, const float* __restrict__ Bb,
    int K, int m0, int n0, int kc, uint32_t bufb, int t)
{
    #pragma unroll
    for (int it = 0; it < 4; ++it) {
        int idx = t + it * 256;          // 0..1023
        int r   = idx >> 3;              // row 0..127
        int sg  = (idx & 7) * 16;        // 16B segment in 128B row
        uint32_t so = (uint32_t)r * TSTRIDE + sg;
        cp16(bufb + so,
             (const char*)(Ab + (size_t)(m0 + r) * K + kc) + sg);
        cp16(bufb + TILE_T + so,
             (const char*)(Bb + (size_t)(n0 + r) * K + kc) + sg);
    }
}

template <int MODE>
__global__ __launch_bounds__(256, 2)
void gemm_tf(const float* __restrict__ A, long long A_bs,
             const float* __restrict__ B, long long B_bs,
             int K, const float* __restrict__ bias,
             const float* __restrict__ resid, float* __restrict__ O)
{
    extern __shared__ char smem[];
    uint32_t sbase = smem_to_u32(smem);
    int t = threadIdx.x;
    int wid = t >> 5, lane = t & 31;
    int m0 = blockIdx.y * 128, n0 = blockIdx.x * 128, z = blockIdx.z;

    const float* Ab = A + (long long)z * A_bs;
    const float* Bb = B + (long long)z * B_bs;

    int wm = wid & 3;       // M offset wm*32
    int wn = wid >> 2;      // N offset wn*64

    // ldsm lane addressing:
    // A frag m16k8: lanes 0-7 rows 0-7 col0 | 8-15 rows 8-15 col0
    //             | 16-23 rows 0-7 col+16B | 24-31 rows 8-15 col+16B
    uint32_t aOff = (uint32_t)(wm * 32 + (lane & 7) + ((lane >> 3) & 1) * 8)
                    * TSTRIDE + ((lane >> 4) & 1) * 16;
    // B frags (2 n8 tiles per ldsm): lanes 0-7 n-rows 0-7 col0 | 8-15 same rows col+16
    //             | 16-23 n-rows 8-15 col0 | 24-31 n-rows 8-15 col+16
    uint32_t bOff = (uint32_t)(wn * 64 + (lane & 7) + ((lane >> 4) & 1) * 8)
                    * TSTRIDE + ((lane >> 3) & 1) * 16 + TILE_T;

    float acc[2][8][4];
    #pragma unroll
    for (int i = 0; i < 2; ++i)
        #pragma unroll
        for (int j = 0; j < 8; ++j)
            #pragma unroll
            for (int c = 0; c < 4; ++c) acc[i][j][c] = 0.f;

    const int NC = K >> 5;

    load_chunk_t(Ab, Bb, K, m0, n0, 0, sbase, t);
    CP_COMMIT();

    for (int i = 0; i < NC; ++i) {
        if (i + 1 < NC) {
            load_chunk_t(Ab, Bb, K, m0, n0, (i + 1) * 32,
                         sbase + ((i + 1) & 1) * STAGE_T, t);
            CP_COMMIT();
            CP_WAIT(1);
        } else {
            CP_WAIT(0);
        }
        __syncthreads();

        uint32_t base = sbase + (i & 1) * STAGE_T;
        #pragma unroll
        for (int kst = 0; kst < 4; ++kst) {
            uint32_t ko = kst * 32;      // 8 fp32 = 32 bytes
            uint32_t a0[4], a1[4];
            ldsm4(a0, base + aOff + ko);
            ldsm4(a1, base + aOff + 16 * TSTRIDE + ko);
            #pragma unroll
            for (int np = 0; np < 4; ++np) {
                uint32_t bb[4];
                ldsm4(bb, base + bOff + np * 16 * TSTRIDE + ko);
                mma_tf32(acc[0][2*np    ], a0, bb[0], bb[1]);
                mma_tf32(acc[0][2*np + 1], a0, bb[2], bb[3]);
                mma_tf32(acc[1][2*np    ], a1, bb[0], bb[1]);
                mma_tf32(acc[1][2*np + 1], a1, bb[2], bb[3]);
            }
        }
        __syncthreads();
    }

    // ---- epilogue: stage acc into smem fp32 [128][132] ----
    float* st = (float*)smem;
    #pragma unroll
    for (int mt = 0; mt < 2; ++mt) {
        int r = wm * 32 + mt * 16 + (lane >> 2);
        #pragma unroll
        for (int nt = 0; nt < 8; ++nt) {
            int c = wn * 64 + nt * 8 + (lane & 3) * 2;
            const float* a = acc[mt][nt];
            if (MODE == 4) {  // transposed staging: st[n][m]
                st[(c    ) * 132 + r    ] = a[0];
                st[(c + 1) * 132 + r    ] = a[1];
                st[(c    ) * 132 + r + 8] = a[2];
                st[(c + 1) * 132 + r + 8] = a[3];
            } else {          // st[m][n]
                st[(r    ) * 132 + c    ] = a[0];
                st[(r    ) * 132 + c + 1] = a[1];
                st[(r + 8) * 132 + c    ] = a[2];
                st[(r + 8) * 132 + c + 1] = a[3];
            }
        }
    }
    __syncthreads();

    if (MODE == 4) {
        for (int idx = t; idx < 4096; idx += 256) {
            int n = idx >> 5, m4 = (idx & 31) * 4;
            size_t a = (size_t)z * 524288 + (size_t)(n0 + n) * 1024 + m0 + m4;
            float bv = __ldg(bias + n0 + n);
            float4 v = *(const float4*)(st + n * 132 + m4);
            float4 rr = *(const float4*)(resid + a);
            v.x += bv + rr.x; v.y += bv + rr.y;
            v.z += bv + rr.z; v.w += bv + rr.w;
            *(float4*)(O + a) = v;
        }
    } else {
        for (int idx = t; idx < 4096; idx += 256) {
            int m = idx >> 5, c4 = (idx & 31) * 4;
            float4 v = *(const float4*)(st + m * 132 + c4);
            size_t off;
            if (MODE == 0) {
                v.x += __ldg(bias + n0 + c4);
                v.y += __ldg(bias + n0 + c4 + 1);
                v.z += __ldg(bias + n0 + c4 + 2);
                v.w += __ldg(bias + n0 + c4 + 3);
                off = (size_t)z * 524288 + (size_t)n0 * 1024
                    + (size_t)(m0 + m) * 128 + c4;
                v.x = to_tf32(v.x); v.y = to_tf32(v.y);
                v.z = to_tf32(v.z); v.w = to_tf32(v.w);
            } else if (MODE == 1) {
                float bv = __ldg(bias + m0 + m);
                v.x += bv; v.y += bv; v.z += bv; v.w += bv;
                off = (size_t)z * 524288 + (size_t)(m0 + m) * 1024 + n0 + c4;
                v.x = to_tf32(v.x); v.y = to_tf32(v.y);
                v.z = to_tf32(v.z); v.w = to_tf32(v.w);
            } else if (MODE == 3) {
                off = (size_t)(z >> 2) * 524288 + (size_t)(m0 + m) * 512
                    + (size_t)(z & 3) * 128 + c4;
                v.x = to_tf32(v.x); v.y = to_tf32(v.y);
                v.z = to_tf32(v.z); v.w = to_tf32(v.w);
            } else { // MODE 2: raw S
                off = (size_t)z * 1048576 + (size_t)(m0 + m) * 1024 + n0 + c4;
            }
            *(float4*)(O + off) = v;
        }
    }
}

// ==================== softmax: S -> P (tf32 fp32) ==========================
__global__ __launch_bounds__(256)
void softmax_kernel(const float* __restrict__ S, float* __restrict__ P)
{
    const float scale = 0.08838834764831844f;  // 1/sqrt(128)
    size_t row = (size_t)blockIdx.x * 8 + (threadIdx.x >> 5);
    int lane = threadIdx.x & 31;
    const float4* src = (const float4*)(S + row * 1024);
    float4 v[8];
    float m = -1e30f;
    #pragma unroll
    for (int j = 0; j < 8; ++j) {
        v[j] = src[j * 32 + lane];
        v[j].x *= scale; v[j].y *= scale; v[j].z *= scale; v[j].w *= scale;
        m = fmaxf(m, fmaxf(fmaxf(v[j].x, v[j].y), fmaxf(v[j].z, v[j].w)));
    }
    #pragma unroll
    for (int o = 16; o; o >>= 1) m = fmaxf(m, __shfl_xor_sync(~0u, m, o));
    float s = 0.f;
    #pragma unroll
    for (int j = 0; j < 8; ++j) {
        v[j].x = __expf(v[j].x - m); v[j].y = __expf(v[j].y - m);
        v[j].z = __expf(v[j].z - m); v[j].w = __expf(v[j].w - m);
        s += v[j].x + v[j].y + v[j].z + v[j].w;
    }
    #pragma unroll
    for (int o = 16; o; o >>= 1) s += __shfl_xor_sync(~0u, s, o);
    float inv = 1.f / s;
    float4* dst = (float4*)(P + row * 1024);
    #pragma unroll
    for (int j = 0; j < 8; ++j) {
        float4 p;
        p.x = to_tf32(v[j].x * inv); p.y = to_tf32(v[j].y * inv);
        p.z = to_tf32(v[j].z * inv); p.w = to_tf32(v[j].w * inv);
        dst[j * 32 + lane] = p;
    }
}

// ==================== launch ================================================
extern "C" void kernel_launch(void* const* d_in, const int* in_sizes, int n_in,
                              void* d_out, int out_size)
{
    const float* x     = (const float*)d_in[0];
    const float* gamma = (const float*)d_in[1];
    const float* beta  = (const float*)d_in[2];
    const float* wq    = (const float*)d_in[3];
    const float* bq    = (const float*)d_in[4];
    const float* wk    = (const float*)d_in[5];
    const float* bk    = (const float*)d_in[6];
    const float* wv    = (const float*)d_in[7];
    const float* bv    = (const float*)d_in[8];
    const float* wp    = (const float*)d_in[9];
    const float* bp    = (const float*)d_in[10];
    float* out = (float*)d_out;

    float *hn, *hnT, *W, *q, *k, *v, *S, *P, *ao;
    cudaGetSymbolAddress((void**)&hn,  g_hn);
    cudaGetSymbolAddress((void**)&hnT, g_hnT);
    cudaGetSymbolAddress((void**)&W,   g_w);
    cudaGetSymbolAddress((void**)&q,   g_q);
    cudaGetSymbolAddress((void**)&k,   g_k);
    cudaGetSymbolAddress((void**)&v,   g_v);
    cudaGetSymbolAddress((void**)&S,   g_S);
    cudaGetSymbolAddress((void**)&P,   g_P);
    cudaGetSymbolAddress((void**)&ao,  g_ao);

    cudaFuncSetAttribute(gemm_tf<0>, cudaFuncAttributeMaxDynamicSharedMemorySize, SMEM_GEMM);
    cudaFuncSetAttribute(gemm_tf<1>, cudaFuncAttributeMaxDynamicSharedMemorySize, SMEM_GEMM);
    cudaFuncSetAttribute(gemm_tf<2>, cudaFuncAttributeMaxDynamicSharedMemorySize, SMEM_GEMM);
    cudaFuncSetAttribute(gemm_tf<3>, cudaFuncAttributeMaxDynamicSharedMemorySize, SMEM_GEMM);
    cudaFuncSetAttribute(gemm_tf<4>, cudaFuncAttributeMaxDynamicSharedMemorySize, SMEM_GEMM);

    gn_kernel<<<BATCH * NGRP, 256>>>(x, gamma, beta, hn);
    t_tf32_kernel<<<dim3(32, 16, BATCH), dim3(32, 8)>>>(hn, hnT);
    wconv_kernel<<<dim3(1024, 4), 256>>>(wq, wk, wv, wp, W);

    const long long HNB = (long long)HWSZ * CCH;     // 524288
    const long long QKB = (long long)HWSZ * HDIM;    // 131072
    const long long WS  = (long long)CCH * CCH;      // 262144

    // Q, K: D[p][o] — A = hnT (M=p), B = W (N=o)
    gemm_tf<0><<<dim3(4, 8, BATCH), 256, SMEM_GEMM>>>(
        hnT, HNB, W + 0 * WS, 0, CCH, bq, nullptr, q);
    gemm_tf<0><<<dim3(4, 8, BATCH), 256, SMEM_GEMM>>>(
        hnT, HNB, W + 1 * WS, 0, CCH, bk, nullptr, k);
    // V: D[o][p] — A = W (M=o), B = hnT (N=p)
    gemm_tf<1><<<dim3(8, 4, BATCH), 256, SMEM_GEMM>>>(
        W + 2 * WS, 0, hnT, HNB, CCH, bv, nullptr, v);
    // S = Q·K^T (raw), stored [z][q][k]
    gemm_tf<2><<<dim3(8, 8, 64), 256, SMEM_GEMM>>>(
        q, QKB, k, QKB, HDIM, nullptr, nullptr, S);
    // softmax (applies scale) -> P tf32
    softmax_kernel<<<8192, 256>>>(S, P);
    // O = P·V^T : D[q][d] -> ao [b][p][c]
    gemm_tf<3><<<dim3(1, 8, 64), 256, SMEM_GEMM>>>(
        P, (long long)HWSZ * HWSZ, v, QKB, HWSZ, nullptr, nullptr, ao);
    // proj + bias + residual -> out [b][o][p]
    gemm_tf<4><<<dim3(4, 8, BATCH), 256, SMEM_GEMM>>>(
        ao, HNB, W + 3 * WS, 0, CCH, bp, x, out);
}

// round 10
// speedup vs baseline: 5.5362x; 1.0081x over previous
#include <cuda_runtime.h>
#include <cstdint>

#define BATCH 16
#define CCH   512
#define HWSZ  1024
#define NHEAD 4
#define HDIM  128
#define NGRP  32
#define CPG   16
#define EPSV  1e-5f

// ======================= PTX helpers ========================================
__device__ __forceinline__ uint32_t smem_to_u32(const void* p) {
    uint32_t a;
    asm("{ .reg .u64 t; cvta.to.shared.u64 t, %1; cvt.u32.u64 %0, t; }"
        : "=r"(a) : "l"(p));
    return a;
}
__device__ __forceinline__ void cp16(uint32_t dst, const void* src) {
    asm volatile("cp.async.cg.shared.global [%0], [%1], 16;"
                 :: "r"(dst), "l"(src));
}
#define CP_COMMIT() asm volatile("cp.async.commit_group;" ::: "memory")
#define CP_WAIT(n)  asm volatile("cp.async.wait_group %0;" :: "n"(n) : "memory")

__device__ __forceinline__ void ldsm4(uint32_t* r, uint32_t addr) {
    asm volatile("ldmatrix.sync.aligned.m8n8.x4.shared.b16 {%0,%1,%2,%3}, [%4];"
                 : "=r"(r[0]), "=r"(r[1]), "=r"(r[2]), "=r"(r[3]) : "r"(addr));
}
__device__ __forceinline__ void mma_tf32(float* c, const uint32_t* a,
                                         uint32_t b0, uint32_t b1) {
    asm volatile(
        "mma.sync.aligned.m16n8k8.row.col.f32.tf32.tf32.f32 "
        "{%0,%1,%2,%3}, {%4,%5,%6,%7}, {%8,%9}, {%0,%1,%2,%3};"
        : "+f"(c[0]), "+f"(c[1]), "+f"(c[2]), "+f"(c[3])
        : "r"(a[0]), "r"(a[1]), "r"(a[2]), "r"(a[3]), "r"(b0), "r"(b1));
}
__device__ __forceinline__ float to_tf32(float x) {
    uint32_t u;
    asm("cvt.rna.tf32.f32 %0, %1;" : "=r"(u) : "f"(x));
    return __uint_as_float(u);
}

// ========================= scratch (static) ================================
__device__ float g_stats[BATCH * NGRP * 2];              // mean, inv per (b,g)
__device__ float g_hnT[BATCH * HWSZ * CCH];              // tf32 [b][p][c]
__device__ float g_w  [4 * CCH * CCH];                   // tf32 weights [o][c]
__device__ float g_q  [BATCH * NHEAD * HWSZ * HDIM];     // [bh][p][d]
__device__ float g_k  [BATCH * NHEAD * HWSZ * HDIM];     // [bh][p][d]
__device__ float g_v  [BATCH * NHEAD * HDIM * HWSZ];     // [bh][d][p]
__device__ float g_ao [BATCH * HWSZ * CCH];              // tf32 [b][p][c]

// ========================= GroupNorm stats =================================
__global__ __launch_bounds__(256)
void gn_stats(const float* __restrict__ x, float* __restrict__ stats)
{
    int bid = blockIdx.x;            // b*32 + g
    size_t base = (size_t)bid * (CPG * HWSZ);
    const float4* xb4 = (const float4*)(x + base);
    int t = threadIdx.x;

    float s = 0.f, ss = 0.f;
    for (int i = t; i < 4096; i += 256) {
        float4 v = xb4[i];
        s  += v.x + v.y + v.z + v.w;
        ss += v.x*v.x + v.y*v.y + v.z*v.z + v.w*v.w;
    }
    __shared__ float rs[8], rss[8];
    int lane = t & 31, wid = t >> 5;
    #pragma unroll
    for (int o = 16; o; o >>= 1) {
        s  += __shfl_xor_sync(~0u, s, o);
        ss += __shfl_xor_sync(~0u, ss, o);
    }
    if (lane == 0) { rs[wid] = s; rss[wid] = ss; }
    __syncthreads();
    if (t == 0) {
        float ts = 0.f, tss = 0.f;
        #pragma unroll
        for (int i = 0; i < 8; ++i) { ts += rs[i]; tss += rss[i]; }
        float mean = ts * (1.f / 16384.f);
        float var  = tss * (1.f / 16384.f) - mean * mean;
        stats[bid * 2]     = mean;
        stats[bid * 2 + 1] = rsqrtf(var + EPSV);
    }
}

// ============ fused normalize + transpose + tf32: x -> hnT =================
__global__ __launch_bounds__(256)
void t_norm_kernel(const float* __restrict__ x, const float* __restrict__ stats,
                   const float* __restrict__ gamma, const float* __restrict__ beta,
                   float* __restrict__ T)
{
    __shared__ float tl[32][33];
    int p0 = blockIdx.x * 32, c0 = blockIdx.y * 32, b = blockIdx.z;
    int tx = threadIdx.x, ty = threadIdx.y;
    #pragma unroll
    for (int j = 0; j < 4; ++j)
        tl[ty + 8*j][tx] = x[((size_t)b*CCH + c0 + ty + 8*j) * HWSZ + p0 + tx];
    __syncthreads();
    int c = c0 + tx;
    int g = c >> 4;
    float mean = stats[(b * 32 + g) * 2];
    float inv  = stats[(b * 32 + g) * 2 + 1];
    float gm = gamma[c] * inv;
    float bt = beta[c] - mean * gm;
    #pragma unroll
    for (int j = 0; j < 4; ++j) {
        size_t o = ((size_t)b*HWSZ + p0 + ty + 8*j) * CCH + c;
        T[o] = to_tf32(tl[tx][ty + 8*j] * gm + bt);
    }
}

// ==================== weight tf32 round =====================================
__global__ __launch_bounds__(256)
void wconv_kernel(const float* __restrict__ W0, const float* __restrict__ W1,
                  const float* __restrict__ W2, const float* __restrict__ W3,
                  float* __restrict__ Wo)
{
    const float* W = blockIdx.y == 0 ? W0 : blockIdx.y == 1 ? W1 :
                     blockIdx.y == 2 ? W2 : W3;
    size_t i = (size_t)blockIdx.x * 256 + threadIdx.x;
    Wo[(size_t)blockIdx.y * (CCH * CCH) + i] = to_tf32(W[i]);
}

// ==================== TF32 conv GEMM (modes 0,1,4) =========================
#define TSTRIDE  144
#define TILE_T   18432
#define STAGE_T  (2 * TILE_T)
#define SMEM_GEMM (2 * STAGE_T)

__device__ __forceinline__ void load_chunk_t(
    const float* __restrict__ Ab, const float* __restrict__ Bb,
    int K, int m0, int n0, int kc, uint32_t bufb, int t)
{
    #pragma unroll
    for (int it = 0; it < 4; ++it) {
        int idx = t + it * 256;
        int r   = idx >> 3;
        int sg  = (idx & 7) * 16;
        uint32_t so = (uint32_t)r * TSTRIDE + sg;
        cp16(bufb + so, (const char*)(Ab + (size_t)(m0 + r) * K + kc) + sg);
        cp16(bufb + TILE_T + so, (const char*)(Bb + (size_t)(n0 + r) * K + kc) + sg);
    }
}

template <int MODE>
__global__ __launch_bounds__(256, 2)
void gemm_tf(const float* __restrict__ A, long long A_bs,
             const float* __restrict__ B, long long B_bs,
             int K, const float* __restrict__ bias,
             const float* __restrict__ resid, float* __restrict__ O)
{
    extern __shared__ char smem[];
    uint32_t sbase = smem_to_u32(smem);
    int t = threadIdx.x;
    int wid = t >> 5, lane = t & 31;
    int m0 = blockIdx.y * 128, n0 = blockIdx.x * 128, z = blockIdx.z;

    const float* Ab = A + (long long)z * A_bs;
    const float* Bb = B + (long long)z * B_bs;

    int wm = wid & 3;
    int wn = wid >> 2;

    uint32_t aOff = (uint32_t)(wm * 32 + (lane & 7) + ((lane >> 3) & 1) * 8)
                    * TSTRIDE + ((lane >> 4) & 1) * 16;
    uint32_t bOff = (uint32_t)(wn * 64 + (lane & 7) + ((lane >> 4) & 1) * 8)
                    * TSTRIDE + ((lane >> 3) & 1) * 16 + TILE_T;

    float acc[2][8][4];
    #pragma unroll
    for (int i = 0; i < 2; ++i)
        #pragma unroll
        for (int j = 0; j < 8; ++j)
            #pragma unroll
            for (int c = 0; c < 4; ++c) acc[i][j][c] = 0.f;

    const int NC = K >> 5;

    load_chunk_t(Ab, Bb, K, m0, n0, 0, sbase, t);
    CP_COMMIT();

    for (int i = 0; i < NC; ++i) {
        if (i + 1 < NC) {
            load_chunk_t(Ab, Bb, K, m0, n0, (i + 1) * 32,
                         sbase + ((i + 1) & 1) * STAGE_T, t);
            CP_COMMIT();
            CP_WAIT(1);
        } else {
            CP_WAIT(0);
        }
        __syncthreads();

        uint32_t base = sbase + (i & 1) * STAGE_T;
        #pragma unroll
        for (int kst = 0; kst < 4; ++kst) {
            uint32_t ko = kst * 32;
            uint32_t a0[4], a1[4];
            ldsm4(a0, base + aOff + ko);
            ldsm4(a1, base + aOff + 16 * TSTRIDE + ko);
            #pragma unroll
            for (int np = 0; np < 4; ++np) {
                uint32_t bb[4];
                ldsm4(bb, base + bOff + np * 16 * TSTRIDE + ko);
                mma_tf32(acc[0][2*np    ], a0, bb[0], bb[1]);
                mma_tf32(acc[0][2*np + 1], a0, bb[2], bb[3]);
                mma_tf32(acc[1][2*np    ], a1, bb[0], bb[1]);
                mma_tf32(acc[1][2*np + 1], a1, bb[2], bb[3]);
            }
        }
        __syncthreads();
    }

    float* st = (float*)smem;
    #pragma unroll
    for (int mt = 0; mt < 2; ++mt) {
        int r = wm * 32 + mt * 16 + (lane >> 2);
        #pragma unroll
        for (int nt = 0; nt < 8; ++nt) {
            int c = wn * 64 + nt * 8 + (lane & 3) * 2;
            const float* a = acc[mt][nt];
            if (MODE == 4) {
                st[(c    ) * 132 + r    ] = a[0];
                st[(c + 1) * 132 + r    ] = a[1];
                st[(c    ) * 132 + r + 8] = a[2];
                st[(c + 1) * 132 + r + 8] = a[3];
            } else {
                st[(r    ) * 132 + c    ] = a[0];
                st[(r    ) * 132 + c + 1] = a[1];
                st[(r + 8) * 132 + c    ] = a[2];
                st[(r + 8) * 132 + c + 1] = a[3];
            }
        }
    }
    __syncthreads();

    if (MODE == 4) {
        for (int idx = t; idx < 4096; idx += 256) {
            int n = idx >> 5, m4 = (idx & 31) * 4;
            size_t a = (size_t)z * 524288 + (size_t)(n0 + n) * 1024 + m0 + m4;
            float bv = __ldg(bias + n0 + n);
            float4 v = *(const float4*)(st + n * 132 + m4);
            float4 rr = *(const float4*)(resid + a);
            v.x += bv + rr.x; v.y += bv + rr.y;
            v.z += bv + rr.z; v.w += bv + rr.w;
            *(float4*)(O + a) = v;
        }
    } else {
        for (int idx = t; idx < 4096; idx += 256) {
            int m = idx >> 5, c4 = (idx & 31) * 4;
            float4 v = *(const float4*)(st + m * 132 + c4);
            size_t off;
            if (MODE == 0) {
                v.x += __ldg(bias + n0 + c4);
                v.y += __ldg(bias + n0 + c4 + 1);
                v.z += __ldg(bias + n0 + c4 + 2);
                v.w += __ldg(bias + n0 + c4 + 3);
                off = (size_t)z * 524288 + (size_t)n0 * 1024
                    + (size_t)(m0 + m) * 128 + c4;
            } else { // MODE 1
                float bv = __ldg(bias + m0 + m);
                v.x += bv; v.y += bv; v.z += bv; v.w += bv;
                off = (size_t)z * 524288 + (size_t)(m0 + m) * 1024 + n0 + c4;
            }
            v.x = to_tf32(v.x); v.y = to_tf32(v.y);
            v.z = to_tf32(v.z); v.w = to_tf32(v.w);
            *(float4*)(O + off) = v;
        }
    }
}

// ==================== fused flash attention =================================
// block = (q-tile 128, bh). 512 threads / 16 warps: wm = wid&3 (32 q rows),
// wn = wid>>2 (S: 16 k cols; AV: 32 d cols). k-tile = 64, 16 iterations.
// Q,K [bh][p][d] K-major(d); V [bh][d][p] K-major(p). Online softmax,
// P staged in smem as tf32, O = (P V) / l written to ao [b][p][h*128+d].
#define QT 128
#define KTILE 64
#define NKT 16
#define QROW 528                 // 512B row + 16B pad (16 mod 128 — ldsm clean)
#define PROW 272                 // 256B row + 16B
#define QS_OFF 0
#define KS_OFF 67584             // 128*528
#define KBUF   33792             // 64*528
#define VS_OFF 135168
#define PS_OFF 169984            // VS + 128*272
#define AL_OFF 204800            // PS + 128*272
#define LI_OFF 205312
#define SMEM_FLASH 205824

__global__ __launch_bounds__(512, 1)
void flash_kernel(const float* __restrict__ Q, const float* __restrict__ K,
                  const float* __restrict__ V, float* __restrict__ AO)
{
    extern __shared__ char smem[];
    uint32_t sb = smem_to_u32(smem);
    int t = threadIdx.x;
    int wid = t >> 5, lane = t & 31;
    int q0 = blockIdx.x * QT;
    int bh = blockIdx.y;
    const char* Qg = (const char*)(Q + (size_t)bh * 131072);
    const char* Kg = (const char*)(K + (size_t)bh * 131072);
    const char* Vg = (const char*)(V + (size_t)bh * 131072);

    int wm = wid & 3, wn = wid >> 2;

    // ---- initial loads: Q (128x512B), K(0) (64x512B), V(0) (128x256B) ----
    #pragma unroll
    for (int it = 0; it < 8; ++it) {
        int idx = t + it * 512;               // 0..4095
        int r = idx >> 5, sg = (idx & 31) * 16;
        cp16(sb + QS_OFF + (uint32_t)r * QROW + sg,
             Qg + (size_t)(q0 + r) * 512 + sg);
    }
    #pragma unroll
    for (int it = 0; it < 4; ++it) {
        int idx = t + it * 512;               // 0..2047
        int r = idx >> 5, sg = (idx & 31) * 16;
        cp16(sb + KS_OFF + (uint32_t)r * QROW + sg, Kg + (size_t)r * 512 + sg);
        int rv = idx >> 4, sgv = (idx & 15) * 16;
        cp16(sb + VS_OFF + (uint32_t)rv * PROW + sgv,
             Vg + (size_t)rv * 4096 + sgv);
    }
    CP_COMMIT();

    // ldsm lane offsets
    uint32_t aQ = sb + QS_OFF
        + (uint32_t)(wm * 32 + (lane & 7) + ((lane >> 3) & 1) * 8) * QROW
        + ((lane >> 4) & 1) * 16;
    uint32_t bK_rel =
          (uint32_t)(wn * 16 + (lane & 7) + ((lane >> 4) & 1) * 8) * QROW
        + ((lane >> 3) & 1) * 16;
    uint32_t aP = sb + PS_OFF
        + (uint32_t)(wm * 32 + (lane & 7) + ((lane >> 3) & 1) * 8) * PROW
        + ((lane >> 4) & 1) * 16;
    uint32_t bV = sb + VS_OFF
        + (uint32_t)(wn * 32 + (lane & 7) + ((lane >> 4) & 1) * 8) * PROW
        + ((lane >> 3) & 1) * 16;

    float oacc[2][4][4];
    #pragma unroll
    for (int i = 0; i < 2; ++i)
        #pragma unroll
        for (int j = 0; j < 4; ++j)
            #pragma unroll
            for (int c = 0; c < 4; ++c) oacc[i][j][c] = 0.f;

    float m_run = -1e30f, l_run = 0.f;
    float* Ps = (float*)(smem + PS_OFF);
    float* al = (float*)(smem + AL_OFF);
    const float scale = 0.08838834764831844f;   // 1/sqrt(128)

    for (int i = 0; i < NKT; ++i) {
        if (i == 0) { CP_WAIT(0); } else { CP_WAIT(1); }   // K(i) ready
        __syncthreads();

        // prefetch K(i+1) into other buffer
        if (i + 1 < NKT) {
            uint32_t kb = sb + KS_OFF + ((i + 1) & 1) * KBUF;
            #pragma unroll
            for (int it = 0; it < 4; ++it) {
                int idx = t + it * 512;
                int r = idx >> 5, sg = (idx & 31) * 16;
                cp16(kb + (uint32_t)r * QROW + sg,
                     Kg + (size_t)((i + 1) * KTILE + r) * 512 + sg);
            }
            CP_COMMIT();
        }

        // ---- S = Q K^T (raw) ----
        float sacc[2][2][4];
        #pragma unroll
        for (int a = 0; a < 2; ++a)
            #pragma unroll
            for (int b = 0; b < 2; ++b)
                #pragma unroll
                for (int c = 0; c < 4; ++c) sacc[a][b][c] = 0.f;

        uint32_t kb = sb + KS_OFF + (i & 1) * KBUF + bK_rel;
        #pragma unroll
        for (int d8 = 0; d8 < 16; ++d8) {
            uint32_t ko = d8 * 32;
            uint32_t a0[4], a1[4], bb[4];
            ldsm4(a0, aQ + ko);
            ldsm4(a1, aQ + 16 * QROW + ko);
            ldsm4(bb, kb + ko);
            mma_tf32(sacc[0][0], a0, bb[0], bb[1]);
            mma_tf32(sacc[0][1], a0, bb[2], bb[3]);
            mma_tf32(sacc[1][0], a1, bb[0], bb[1]);
            mma_tf32(sacc[1][1], a1, bb[2], bb[3]);
        }

        // ---- stage raw S to Ps ----
        #pragma unroll
        for (int mt = 0; mt < 2; ++mt) {
            int rr = wm * 32 + mt * 16 + (lane >> 2);
            #pragma unroll
            for (int nt = 0; nt < 2; ++nt) {
                int cc = wn * 16 + nt * 8 + (lane & 3) * 2;
                Ps[rr * 68 + cc]           = sacc[mt][nt][0];
                Ps[rr * 68 + cc + 1]       = sacc[mt][nt][1];
                Ps[(rr + 8) * 68 + cc]     = sacc[mt][nt][2];
                Ps[(rr + 8) * 68 + cc + 1] = sacc[mt][nt][3];
            }
        }
        __syncthreads();

        // ---- online softmax (4 threads per row) ----
        {
            int r = t >> 2, qd = t & 3;
            float* prow = Ps + r * 68 + qd * 16;
            float4 vv[4];
            float mx = -1e30f;
            #pragma unroll
            for (int j = 0; j < 4; ++j) {
                vv[j] = ((float4*)prow)[j];
                vv[j].x *= scale; vv[j].y *= scale;
                vv[j].z *= scale; vv[j].w *= scale;
                mx = fmaxf(mx, fmaxf(fmaxf(vv[j].x, vv[j].y),
                                     fmaxf(vv[j].z, vv[j].w)));
            }
            mx = fmaxf(mx, __shfl_xor_sync(~0u, mx, 1));
            mx = fmaxf(mx, __shfl_xor_sync(~0u, mx, 2));
            float m_new = fmaxf(m_run, mx);
            float sum = 0.f;
            #pragma unroll
            for (int j = 0; j < 4; ++j) {
                float4 e;
                e.x = __expf(vv[j].x - m_new); e.y = __expf(vv[j].y - m_new);
                e.z = __expf(vv[j].z - m_new); e.w = __expf(vv[j].w - m_new);
                sum += e.x + e.y + e.z + e.w;
                e.x = to_tf32(e.x); e.y = to_tf32(e.y);
                e.z = to_tf32(e.z); e.w = to_tf32(e.w);
                ((float4*)prow)[j] = e;
            }
            sum += __shfl_xor_sync(~0u, sum, 1);
            sum += __shfl_xor_sync(~0u, sum, 2);
            float alpha = __expf(m_run - m_new);
            l_run = l_run * alpha + sum;
            m_run = m_new;
            if (qd == 0) al[r] = alpha;
        }

        // V(i) must be ready; Ps/alpha visible to all
        if (i + 1 < NKT) { CP_WAIT(1); } else { CP_WAIT(0); }
        __syncthreads();

        // ---- rescale O by alpha ----
        #pragma unroll
        for (int mt = 0; mt < 2; ++mt) {
            int rr = wm * 32 + mt * 16 + (lane >> 2);
            float a0 = al[rr], a1 = al[rr + 8];
            #pragma unroll
            for (int nt = 0; nt < 4; ++nt) {
                oacc[mt][nt][0] *= a0; oacc[mt][nt][1] *= a0;
                oacc[mt][nt][2] *= a1; oacc[mt][nt][3] *= a1;
            }
        }

        // ---- O += P V ----
        #pragma unroll
        for (int k8 = 0; k8 < 8; ++k8) {
            uint32_t ko = k8 * 32;
            uint32_t a0[4], a1[4];
            ldsm4(a0, aP + ko);
            ldsm4(a1, aP + 16 * PROW + ko);
            #pragma unroll
            for (int np = 0; np < 2; ++np) {
                uint32_t bb[4];
                ldsm4(bb, bV + np * 16 * PROW + ko);
                mma_tf32(oacc[0][2*np    ], a0, bb[0], bb[1]);
                mma_tf32(oacc[0][2*np + 1], a0, bb[2], bb[3]);
                mma_tf32(oacc[1][2*np    ], a1, bb[0], bb[1]);
                mma_tf32(oacc[1][2*np + 1], a1, bb[2], bb[3]);
            }
        }
        __syncthreads();      // Vs consumed by all warps

        // prefetch V(i+1)
        if (i + 1 < NKT) {
            #pragma unroll
            for (int it = 0; it < 4; ++it) {
                int idx = t + it * 512;
                int rv = idx >> 4, sgv = (idx & 15) * 16;
                cp16(sb + VS_OFF + (uint32_t)rv * PROW + sgv,
                     Vg + (size_t)rv * 4096 + (size_t)(i + 1) * (KTILE * 4) + sgv);
            }
            CP_COMMIT();
        }
    }

    // ---- finalize: 1/l, stage O, write ao ----
    {
        int r = t >> 2;
        if ((t & 3) == 0) ((float*)(smem + LI_OFF))[r] = 1.f / l_run;
    }
    __syncthreads();

    float* st = (float*)smem;                 // reuse Qs region (67584B ≥ 128*132*4)
    float* li = (float*)(smem + LI_OFF);
    #pragma unroll
    for (int mt = 0; mt < 2; ++mt) {
        int rr = wm * 32 + mt * 16 + (lane >> 2);
        float li0 = li[rr], li1 = li[rr + 8];
        #pragma unroll
        for (int nt = 0; nt < 4; ++nt) {
            int cc = wn * 32 + nt * 8 + (lane & 3) * 2;
            st[rr * 132 + cc]           = oacc[mt][nt][0] * li0;
            st[rr * 132 + cc + 1]       = oacc[mt][nt][1] * li0;
            st[(rr + 8) * 132 + cc]     = oacc[mt][nt][2] * li1;
            st[(rr + 8) * 132 + cc + 1] = oacc[mt][nt][3] * li1;
        }
    }
    __syncthreads();

    float* aob = AO + (size_t)(bh >> 2) * 524288 + (size_t)(bh & 3) * 128;
    for (int idx = t; idx < 4096; idx += 512) {
        int m = idx >> 5, c4 = (idx & 31) * 4;
        float4 v = *(const float4*)(st + m * 132 + c4);
        v.x = to_tf32(v.x); v.y = to_tf32(v.y);
        v.z = to_tf32(v.z); v.w = to_tf32(v.w);
        *(float4*)(aob + (size_t)(q0 + m) * 512 + c4) = v;
    }
}

// ==================== launch ================================================
extern "C" void kernel_launch(void* const* d_in, const int* in_sizes, int n_in,
                              void* d_out, int out_size)
{
    const float* x     = (const float*)d_in[0];
    const float* gamma = (const float*)d_in[1];
    const float* beta  = (const float*)d_in[2];
    const float* wq    = (const float*)d_in[3];
    const float* bq    = (const float*)d_in[4];
    const float* wk    = (const float*)d_in[5];
    const float* bk    = (const float*)d_in[6];
    const float* wv    = (const float*)d_in[7];
    const float* bv    = (const float*)d_in[8];
    const float* wp    = (const float*)d_in[9];
    const float* bp    = (const float*)d_in[10];
    float* out = (float*)d_out;

    float *stats, *hnT, *W, *q, *k, *v, *ao;
    cudaGetSymbolAddress((void**)&stats, g_stats);
    cudaGetSymbolAddress((void**)&hnT, g_hnT);
    cudaGetSymbolAddress((void**)&W,   g_w);
    cudaGetSymbolAddress((void**)&q,   g_q);
    cudaGetSymbolAddress((void**)&k,   g_k);
    cudaGetSymbolAddress((void**)&v,   g_v);
    cudaGetSymbolAddress((void**)&ao,  g_ao);

    cudaFuncSetAttribute(gemm_tf<0>, cudaFuncAttributeMaxDynamicSharedMemorySize, SMEM_GEMM);
    cudaFuncSetAttribute(gemm_tf<1>, cudaFuncAttributeMaxDynamicSharedMemorySize, SMEM_GEMM);
    cudaFuncSetAttribute(gemm_tf<4>, cudaFuncAttributeMaxDynamicSharedMemorySize, SMEM_GEMM);
    cudaFuncSetAttribute(flash_kernel, cudaFuncAttributeMaxDynamicSharedMemorySize, SMEM_FLASH);

    gn_stats<<<BATCH * NGRP, 256>>>(x, stats);
    t_norm_kernel<<<dim3(32, 16, BATCH), dim3(32, 8)>>>(x, stats, gamma, beta, hnT);
    wconv_kernel<<<dim3(1024, 4), 256>>>(wq, wk, wv, wp, W);

    const long long HNB = (long long)HWSZ * CCH;     // 524288
    const long long WS  = (long long)CCH * CCH;      // 262144

    // Q, K: [bh][p][d]
    gemm_tf<0><<<dim3(4, 8, BATCH), 256, SMEM_GEMM>>>(
        hnT, HNB, W + 0 * WS, 0, CCH, bq, nullptr, q);
    gemm_tf<0><<<dim3(4, 8, BATCH), 256, SMEM_GEMM>>>(
        hnT, HNB, W + 1 * WS, 0, CCH, bk, nullptr, k);
    // V: [bh][d][p]
    gemm_tf<1><<<dim3(8, 4, BATCH), 256, SMEM_GEMM>>>(
        W + 2 * WS, 0, hnT, HNB, CCH, bv, nullptr, v);
    // fused attention -> ao [b][p][c]
    flash_kernel<<<dim3(8, 64), 512, SMEM_FLASH>>>(q, k, v, ao);
    // proj + bias + residual -> out [b][o][p]
    gemm_tf<4><<<dim3(4, 8, BATCH), 256, SMEM_GEMM>>>(
        ao, HNB, W + 3 * WS, 0, CCH, bp, x, out);
}

// round 11
// speedup vs baseline: 5.8185x; 1.0510x over previous
#include <cuda_runtime.h>
#include <cstdint>

#define BATCH 16
#define CCH   512
#define HWSZ  1024
#define NHEAD 4
#define HDIM  128
#define NGRP  32
#define CPG   16
#define EPSV  1e-5f

// ======================= PTX helpers ========================================
__device__ __forceinline__ uint32_t smem_to_u32(const void* p) {
    uint32_t a;
    asm("{ .reg .u64 t; cvta.to.shared.u64 t, %1; cvt.u32.u64 %0, t; }"
        : "=r"(a) : "l"(p));
    return a;
}
__device__ __forceinline__ void cp16(uint32_t dst, const void* src) {
    asm volatile("cp.async.cg.shared.global [%0], [%1], 16;"
                 :: "r"(dst), "l"(src));
}
#define CP_COMMIT() asm volatile("cp.async.commit_group;" ::: "memory")
#define CP_WAIT(n)  asm volatile("cp.async.wait_group %0;" :: "n"(n) : "memory")
#define GROUP_BAR(id) asm volatile("bar.sync %0, 256;" :: "r"(id) : "memory")

__device__ __forceinline__ void ldsm4(uint32_t* r, uint32_t addr) {
    asm volatile("ldmatrix.sync.aligned.m8n8.x4.shared.b16 {%0,%1,%2,%3}, [%4];"
                 : "=r"(r[0]), "=r"(r[1]), "=r"(r[2]), "=r"(r[3]) : "r"(addr));
}
__device__ __forceinline__ void mma_tf32(float* c, const uint32_t* a,
                                         uint32_t b0, uint32_t b1) {
    asm volatile(
        "mma.sync.aligned.m16n8k8.row.col.f32.tf32.tf32.f32 "
        "{%0,%1,%2,%3}, {%4,%5,%6,%7}, {%8,%9}, {%0,%1,%2,%3};"
        : "+f"(c[0]), "+f"(c[1]), "+f"(c[2]), "+f"(c[3])
        : "r"(a[0]), "r"(a[1]), "r"(a[2]), "r"(a[3]), "r"(b0), "r"(b1));
}
__device__ __forceinline__ float to_tf32(float x) {
    uint32_t u;
    asm("cvt.rna.tf32.f32 %0, %1;" : "=r"(u) : "f"(x));
    return __uint_as_float(u);
}

// ========================= scratch (static) ================================
__device__ float g_stats[BATCH * NGRP * 2];
__device__ float g_hnT[BATCH * HWSZ * CCH];              // tf32 [b][p][c]
__device__ float g_w  [4 * CCH * CCH];                   // tf32 weights [o][c]
__device__ float g_q  [BATCH * NHEAD * HWSZ * HDIM];     // [bh][p][d]
__device__ float g_k  [BATCH * NHEAD * HWSZ * HDIM];     // [bh][p][d]
__device__ float g_v  [BATCH * NHEAD * HDIM * HWSZ];     // [bh][d][p]
__device__ float g_ao [BATCH * HWSZ * CCH];              // tf32 [b][p][c]

// ========================= GroupNorm stats =================================
__global__ __launch_bounds__(256)
void gn_stats(const float* __restrict__ x, float* __restrict__ stats)
{
    int bid = blockIdx.x;
    size_t base = (size_t)bid * (CPG * HWSZ);
    const float4* xb4 = (const float4*)(x + base);
    int t = threadIdx.x;

    float s = 0.f, ss = 0.f;
    for (int i = t; i < 4096; i += 256) {
        float4 v = xb4[i];
        s  += v.x + v.y + v.z + v.w;
        ss += v.x*v.x + v.y*v.y + v.z*v.z + v.w*v.w;
    }
    __shared__ float rs[8], rss[8];
    int lane = t & 31, wid = t >> 5;
    #pragma unroll
    for (int o = 16; o; o >>= 1) {
        s  += __shfl_xor_sync(~0u, s, o);
        ss += __shfl_xor_sync(~0u, ss, o);
    }
    if (lane == 0) { rs[wid] = s; rss[wid] = ss; }
    __syncthreads();
    if (t == 0) {
        float ts = 0.f, tss = 0.f;
        #pragma unroll
        for (int i = 0; i < 8; ++i) { ts += rs[i]; tss += rss[i]; }
        float mean = ts * (1.f / 16384.f);
        float var  = tss * (1.f / 16384.f) - mean * mean;
        stats[bid * 2]     = mean;
        stats[bid * 2 + 1] = rsqrtf(var + EPSV);
    }
}

// ============ fused normalize + transpose + tf32: x -> hnT =================
__global__ __launch_bounds__(256)
void t_norm_kernel(const float* __restrict__ x, const float* __restrict__ stats,
                   const float* __restrict__ gamma, const float* __restrict__ beta,
                   float* __restrict__ T)
{
    __shared__ float tl[32][33];
    int p0 = blockIdx.x * 32, c0 = blockIdx.y * 32, b = blockIdx.z;
    int tx = threadIdx.x, ty = threadIdx.y;
    #pragma unroll
    for (int j = 0; j < 4; ++j)
        tl[ty + 8*j][tx] = x[((size_t)b*CCH + c0 + ty + 8*j) * HWSZ + p0 + tx];
    __syncthreads();
    int c = c0 + tx;
    int g = c >> 4;
    float mean = stats[(b * 32 + g) * 2];
    float inv  = stats[(b * 32 + g) * 2 + 1];
    float gm = gamma[c] * inv;
    float bt = beta[c] - mean * gm;
    #pragma unroll
    for (int j = 0; j < 4; ++j) {
        size_t o = ((size_t)b*HWSZ + p0 + ty + 8*j) * CCH + c;
        T[o] = to_tf32(tl[tx][ty + 8*j] * gm + bt);
    }
}

// ==================== weight tf32 round =====================================
__global__ __launch_bounds__(256)
void wconv_kernel(const float* __restrict__ W0, const float* __restrict__ W1,
                  const float* __restrict__ W2, const float* __restrict__ W3,
                  float* __restrict__ Wo)
{
    const float* W = blockIdx.y == 0 ? W0 : blockIdx.y == 1 ? W1 :
                     blockIdx.y == 2 ? W2 : W3;
    size_t i = (size_t)blockIdx.x * 256 + threadIdx.x;
    Wo[(size_t)blockIdx.y * (CCH * CCH) + i] = to_tf32(W[i]);
}

// ==================== TF32 conv GEMM (modes 0,1,4), 3-stage ================
#define TSTRIDE  144
#define TILE_T   18432
#define STAGE_T  (2 * TILE_T)
#define SMEM_GEMM (3 * STAGE_T)      // 110592

__device__ __forceinline__ void load_chunk_t(
    const float* __restrict__ Ab, const float* __restrict__ Bb,
    int K, int m0, int n0, int kc, uint32_t bufb, int t)
{
    #pragma unroll
    for (int it = 0; it < 4; ++it) {
        int idx = t + it * 256;
        int r   = idx >> 3;
        int sg  = (idx & 7) * 16;
        uint32_t so = (uint32_t)r * TSTRIDE + sg;
        cp16(bufb + so, (const char*)(Ab + (size_t)(m0 + r) * K + kc) + sg);
        cp16(bufb + TILE_T + so, (const char*)(Bb + (size_t)(n0 + r) * K + kc) + sg);
    }
}

template <int MODE>
__global__ __launch_bounds__(256, 2)
void gemm_tf(const float* __restrict__ A, long long A_bs,
             const float* __restrict__ B, long long B_bs,
             int K, const float* __restrict__ bias,
             const float* __restrict__ resid, float* __restrict__ O)
{
    extern __shared__ char smem[];
    uint32_t sbase = smem_to_u32(smem);
    int t = threadIdx.x;
    int wid = t >> 5, lane = t & 31;
    int m0 = blockIdx.y * 128, n0 = blockIdx.x * 128, z = blockIdx.z;

    const float* Ab = A + (long long)z * A_bs;
    const float* Bb = B + (long long)z * B_bs;

    int wm = wid & 3;
    int wn = wid >> 2;

    uint32_t aOff = (uint32_t)(wm * 32 + (lane & 7) + ((lane >> 3) & 1) * 8)
                    * TSTRIDE + ((lane >> 4) & 1) * 16;
    uint32_t bOff = (uint32_t)(wn * 64 + (lane & 7) + ((lane >> 4) & 1) * 8)
                    * TSTRIDE + ((lane >> 3) & 1) * 16 + TILE_T;

    float acc[2][8][4];
    #pragma unroll
    for (int i = 0; i < 2; ++i)
        #pragma unroll
        for (int j = 0; j < 8; ++j)
            #pragma unroll
            for (int c = 0; c < 4; ++c) acc[i][j][c] = 0.f;

    const int NC = K >> 5;

    load_chunk_t(Ab, Bb, K, m0, n0, 0, sbase, t);
    CP_COMMIT();
    load_chunk_t(Ab, Bb, K, m0, n0, 32, sbase + STAGE_T, t);
    CP_COMMIT();

    for (int i = 0; i < NC; ++i) {
        if (i + 1 < NC) { CP_WAIT(1); } else { CP_WAIT(0); }
        __syncthreads();            // chunk i visible; all done computing i-1
        if (i + 2 < NC) {
            load_chunk_t(Ab, Bb, K, m0, n0, (i + 2) * 32,
                         sbase + ((i + 2) % 3) * STAGE_T, t);
            CP_COMMIT();
        }

        uint32_t base = sbase + (i % 3) * STAGE_T;
        #pragma unroll
        for (int kst = 0; kst < 4; ++kst) {
            uint32_t ko = kst * 32;
            uint32_t a0[4], a1[4];
            ldsm4(a0, base + aOff + ko);
            ldsm4(a1, base + aOff + 16 * TSTRIDE + ko);
            #pragma unroll
            for (int np = 0; np < 4; ++np) {
                uint32_t bb[4];
                ldsm4(bb, base + bOff + np * 16 * TSTRIDE + ko);
                mma_tf32(acc[0][2*np    ], a0, bb[0], bb[1]);
                mma_tf32(acc[0][2*np + 1], a0, bb[2], bb[3]);
                mma_tf32(acc[1][2*np    ], a1, bb[0], bb[1]);
                mma_tf32(acc[1][2*np + 1], a1, bb[2], bb[3]);
            }
        }
    }
    __syncthreads();   // all compute done before st overwrites buffers

    float* st = (float*)smem;
    #pragma unroll
    for (int mt = 0; mt < 2; ++mt) {
        int r = wm * 32 + mt * 16 + (lane >> 2);
        #pragma unroll
        for (int nt = 0; nt < 8; ++nt) {
            int c = wn * 64 + nt * 8 + (lane & 3) * 2;
            const float* a = acc[mt][nt];
            if (MODE == 4) {
                st[(c    ) * 132 + r    ] = a[0];
                st[(c + 1) * 132 + r    ] = a[1];
                st[(c    ) * 132 + r + 8] = a[2];
                st[(c + 1) * 132 + r + 8] = a[3];
            } else {
                st[(r    ) * 132 + c    ] = a[0];
                st[(r    ) * 132 + c + 1] = a[1];
                st[(r + 8) * 132 + c    ] = a[2];
                st[(r + 8) * 132 + c + 1] = a[3];
            }
        }
    }
    __syncthreads();

    if (MODE == 4) {
        for (int idx = t; idx < 4096; idx += 256) {
            int n = idx >> 5, m4 = (idx & 31) * 4;
            size_t a = (size_t)z * 524288 + (size_t)(n0 + n) * 1024 + m0 + m4;
            float bv = __ldg(bias + n0 + n);
            float4 v = *(const float4*)(st + n * 132 + m4);
            float4 rr = *(const float4*)(resid + a);
            v.x += bv + rr.x; v.y += bv + rr.y;
            v.z += bv + rr.z; v.w += bv + rr.w;
            *(float4*)(O + a) = v;
        }
    } else {
        for (int idx = t; idx < 4096; idx += 256) {
            int m = idx >> 5, c4 = (idx & 31) * 4;
            float4 v = *(const float4*)(st + m * 132 + c4);
            size_t off;
            if (MODE == 0) {
                v.x += __ldg(bias + n0 + c4);
                v.y += __ldg(bias + n0 + c4 + 1);
                v.z += __ldg(bias + n0 + c4 + 2);
                v.w += __ldg(bias + n0 + c4 + 3);
                off = (size_t)z * 524288 + (size_t)n0 * 1024
                    + (size_t)(m0 + m) * 128 + c4;
            } else { // MODE 1
                float bv = __ldg(bias + m0 + m);
                v.x += bv; v.y += bv; v.z += bv; v.w += bv;
                off = (size_t)z * 524288 + (size_t)(m0 + m) * 1024 + n0 + c4;
            }
            v.x = to_tf32(v.x); v.y = to_tf32(v.y);
            v.z = to_tf32(v.z); v.w = to_tf32(v.w);
            *(float4*)(O + off) = v;
        }
    }
}

// ==================== fused flash attention (dual-group) ====================
// block = (q-tile 128, bh), 512 thr / 16 warps, 2 groups of 8 warps.
// Group g owns q rows [g*64, g*64+64); groups share double-buffered K,V.
// Swizzled smem: addr = (row*STRIDE + byteCol) ^ ((row&7)<<4).
// Per group per k-tile(64): S = Q K^T -> P smem -> online softmax -> O += P V.
#define QS_O 0                        // Q: 128 x 512B swizzled
#define KS_O 65536                    // K: 2 bufs x 64 x 512B
#define VS_O 131072                   // V: 2 bufs x 128 x 256B
#define PS_O 196608                   // P: 2 groups x 64 x 256B
#define PBUF 16384
#define AL_O 229376                   // alpha[128]
#define LI_O 229888                   // 1/l [128]
#define SMEM_FLASH 230400

__global__ __launch_bounds__(512, 1)
void flash_kernel(const float* __restrict__ Q, const float* __restrict__ K,
                  const float* __restrict__ V, float* __restrict__ AO)
{
    extern __shared__ char smem[];
    uint32_t sb = smem_to_u32(smem);
    int t = threadIdx.x;
    int wid = t >> 5, lane = t & 31;
    int q0 = blockIdx.x * 128;
    int bh = blockIdx.y;
    const char* Qg = (const char*)(Q + (size_t)bh * 131072);
    const char* Kg = (const char*)(K + (size_t)bh * 131072);
    const char* Vg = (const char*)(V + (size_t)bh * 131072);

    int g = wid >> 3, w = wid & 7;
    int wql = (w & 1) * 32;            // q offset within group (S & PV M-dim)
    int wkl = (w >> 1) * 16;           // k offset (S N-dim)
    int wdl = (w >> 1) * 32;           // d offset (PV N-dim)

    // ---- initial loads (swizzled) ----
    #pragma unroll
    for (int it = 0; it < 8; ++it) {
        int idx = t + it * 512;                 // Q: 128 rows x 32 segs
        int r = idx >> 5, sg = (idx & 31) * 16;
        cp16(sb + QS_O + (((uint32_t)r * 512 + sg) ^ ((r & 7) << 4)),
             Qg + (size_t)(q0 + r) * 512 + sg);
    }
    #pragma unroll
    for (int it = 0; it < 4; ++it) {
        int idx = t + it * 512;
        int r = idx >> 5, sg = (idx & 31) * 16;     // K: 64 rows x 32 segs
        cp16(sb + KS_O + (((uint32_t)r * 512 + sg) ^ ((r & 7) << 4)),
             Kg + (size_t)r * 512 + sg);
        int rv = idx >> 4, sgv = (idx & 15) * 16;   // V: 128 rows x 16 segs
        cp16(sb + VS_O + (((uint32_t)rv * 256 + sgv) ^ ((rv & 7) << 4)),
             Vg + (size_t)rv * 4096 + sgv);
    }
    CP_COMMIT();

    // ldsm lane bases (linear; XOR rx applied per access)
    uint32_t rx = (uint32_t)(lane & 7) << 4;
    int arow = (lane & 7) + ((lane >> 3) & 1) * 8;
    int aseg = ((lane >> 4) & 1) * 16;
    int brow = (lane & 7) + ((lane >> 4) & 1) * 8;
    int bseg = ((lane >> 3) & 1) * 16;
    uint32_t aQ = sb + QS_O + (uint32_t)(g * 64 + wql + arow) * 512 + aseg;
    uint32_t bK = (uint32_t)(wkl + brow) * 512 + bseg;              // + KS + buf
    uint32_t aP = sb + PS_O + g * PBUF + (uint32_t)(wql + arow) * 256 + aseg;
    uint32_t bV = (uint32_t)(wdl + brow) * 256 + bseg;              // + VS + buf

    float oacc[2][4][4];
    #pragma unroll
    for (int i = 0; i < 2; ++i)
        #pragma unroll
        for (int j = 0; j < 4; ++j)
            #pragma unroll
            for (int c = 0; c < 4; ++c) oacc[i][j][c] = 0.f;

    float m_run = -1e30f, l_run = 0.f;
    float* al = (float*)(smem + AL_O);
    float* li = (float*)(smem + LI_O);
    int r_loc = (t & 255) >> 2;        // softmax row within group
    int qd = t & 3;
    int gr = t >> 2;                   // global row 0..127
    const float scale = 0.08838834764831844f;

    for (int i = 0; i < 16; ++i) {
        __syncthreads();               // all done with old bufs / prev P
        if (i + 1 < 16) {
            uint32_t kb = sb + KS_O + ((i + 1) & 1) * 32768;
            uint32_t vb = sb + VS_O + ((i + 1) & 1) * 32768;
            #pragma unroll
            for (int it = 0; it < 4; ++it) {
                int idx = t + it * 512;
                int r = idx >> 5, sg = (idx & 31) * 16;
                cp16(kb + (((uint32_t)r * 512 + sg) ^ ((r & 7) << 4)),
                     Kg + (size_t)((i + 1) * 64 + r) * 512 + sg);
                int rv = idx >> 4, sgv = (idx & 15) * 16;
                cp16(vb + (((uint32_t)rv * 256 + sgv) ^ ((rv & 7) << 4)),
                     Vg + (size_t)rv * 4096 + (size_t)(i + 1) * 256 + sgv);
            }
            CP_COMMIT();
            CP_WAIT(1);
        } else {
            CP_WAIT(0);
        }
        __syncthreads();               // K(i), V(i) visible block-wide

        // ---- S = Q K^T ----
        float sacc[2][2][4];
        #pragma unroll
        for (int a = 0; a < 2; ++a)
            #pragma unroll
            for (int b = 0; b < 2; ++b)
                #pragma unroll
                for (int c = 0; c < 4; ++c) sacc[a][b][c] = 0.f;

        uint32_t kb = sb + KS_O + (i & 1) * 32768 + bK;
        #pragma unroll
        for (int d8 = 0; d8 < 16; ++d8) {
            uint32_t ko = d8 * 32;
            uint32_t a0[4], a1[4], bb[4];
            ldsm4(a0, (aQ + ko) ^ rx);
            ldsm4(a1, (aQ + 16 * 512 + ko) ^ rx);
            ldsm4(bb, (kb + ko) ^ rx);
            mma_tf32(sacc[0][0], a0, bb[0], bb[1]);
            mma_tf32(sacc[0][1], a0, bb[2], bb[3]);
            mma_tf32(sacc[1][0], a1, bb[0], bb[1]);
            mma_tf32(sacc[1][1], a1, bb[2], bb[3]);
        }

        // ---- stage S to P (group region, swizzled) ----
        {
            int lr2 = lane >> 2, lc2 = (lane & 3) * 2;
            #pragma unroll
            for (int mt = 0; mt < 2; ++mt) {
                int rr = wql + mt * 16 + lr2;
                uint32_t rxs = ((uint32_t)(rr & 7) << 4);
                #pragma unroll
                for (int nt = 0; nt < 2; ++nt) {
                    int cc = wkl + nt * 8 + lc2;
                    uint32_t o0 = ((uint32_t)(PS_O + g * PBUF + rr * 256 + cc * 4)) ^ rxs;
                    uint32_t o1 = ((uint32_t)(PS_O + g * PBUF + (rr + 8) * 256 + cc * 4)) ^ rxs;
                    *(float2*)(smem + o0) = make_float2(sacc[mt][nt][0], sacc[mt][nt][1]);
                    *(float2*)(smem + o1) = make_float2(sacc[mt][nt][2], sacc[mt][nt][3]);
                }
            }
        }
        GROUP_BAR(g + 1);

        // ---- online softmax (group rows only) ----
        {
            uint32_t rxs = ((uint32_t)(r_loc & 7) << 4);
            uint32_t pbase = (uint32_t)(PS_O + g * PBUF + r_loc * 256 + qd * 64);
            float4 vv[4];
            float mx = -1e30f;
            #pragma unroll
            for (int j = 0; j < 4; ++j) {
                vv[j] = *(float4*)(smem + ((pbase + j * 16) ^ rxs));
                vv[j].x *= scale; vv[j].y *= scale;
                vv[j].z *= scale; vv[j].w *= scale;
                mx = fmaxf(mx, fmaxf(fmaxf(vv[j].x, vv[j].y),
                                     fmaxf(vv[j].z, vv[j].w)));
            }
            mx = fmaxf(mx, __shfl_xor_sync(~0u, mx, 1));
            mx = fmaxf(mx, __shfl_xor_sync(~0u, mx, 2));
            float m_new = fmaxf(m_run, mx);
            float sum = 0.f;
            #pragma unroll
            for (int j = 0; j < 4; ++j) {
                float4 e;
                e.x = __expf(vv[j].x - m_new); e.y = __expf(vv[j].y - m_new);
                e.z = __expf(vv[j].z - m_new); e.w = __expf(vv[j].w - m_new);
                sum += e.x + e.y + e.z + e.w;
                e.x = to_tf32(e.x); e.y = to_tf32(e.y);
                e.z = to_tf32(e.z); e.w = to_tf32(e.w);
                *(float4*)(smem + ((pbase + j * 16) ^ rxs)) = e;
            }
            sum += __shfl_xor_sync(~0u, sum, 1);
            sum += __shfl_xor_sync(~0u, sum, 2);
            float alpha = __expf(m_run - m_new);
            l_run = l_run * alpha + sum;
            m_run = m_new;
            if (qd == 0) al[gr] = alpha;
        }
        GROUP_BAR(g + 1);

        // ---- rescale O, then O += P V ----
        #pragma unroll
        for (int mt = 0; mt < 2; ++mt) {
            int rr = wql + mt * 16 + (lane >> 2);
            float a0 = al[g * 64 + rr], a1 = al[g * 64 + rr + 8];
            #pragma unroll
            for (int nt = 0; nt < 4; ++nt) {
                oacc[mt][nt][0] *= a0; oacc[mt][nt][1] *= a0;
                oacc[mt][nt][2] *= a1; oacc[mt][nt][3] *= a1;
            }
        }
        uint32_t vb = sb + VS_O + (i & 1) * 32768 + bV;
        #pragma unroll
        for (int k8 = 0; k8 < 8; ++k8) {
            uint32_t ko = k8 * 32;
            uint32_t a0[4], a1[4];
            ldsm4(a0, (aP + ko) ^ rx);
            ldsm4(a1, (aP + 16 * 256 + ko) ^ rx);
            #pragma unroll
            for (int np = 0; np < 2; ++np) {
                uint32_t bb[4];
                ldsm4(bb, (vb + np * 16 * 256 + ko) ^ rx);
                mma_tf32(oacc[0][2*np    ], a0, bb[0], bb[1]);
                mma_tf32(oacc[0][2*np + 1], a0, bb[2], bb[3]);
                mma_tf32(oacc[1][2*np    ], a1, bb[0], bb[1]);
                mma_tf32(oacc[1][2*np + 1], a1, bb[2], bb[3]);
            }
        }
    }

    // ---- finalize ----
    if (qd == 0) li[gr] = 1.f / l_run;
    __syncthreads();

    float* st = (float*)smem;          // 128x132 fp32, overwrites Q/K (dead)
    #pragma unroll
    for (int mt = 0; mt < 2; ++mt) {
        int rr = wql + mt * 16 + (lane >> 2);
        int grr = g * 64 + rr;
        float li0 = li[grr], li1 = li[grr + 8];
        #pragma unroll
        for (int nt = 0; nt < 4; ++nt) {
            int cc = wdl + nt * 8 + (lane & 3) * 2;
            st[grr * 132 + cc]           = oacc[mt][nt][0] * li0;
            st[grr * 132 + cc + 1]       = oacc[mt][nt][1] * li0;
            st[(grr + 8) * 132 + cc]     = oacc[mt][nt][2] * li1;
            st[(grr + 8) * 132 + cc + 1] = oacc[mt][nt][3] * li1;
        }
    }
    __syncthreads();

    float* aob = AO + (size_t)(bh >> 2) * 524288 + (size_t)(bh & 3) * 128;
    for (int idx = t; idx < 4096; idx += 512) {
        int m = idx >> 5, c4 = (idx & 31) * 4;
        float4 v = *(const float4*)(st + m * 132 + c4);
        v.x = to_tf32(v.x); v.y = to_tf32(v.y);
        v.z = to_tf32(v.z); v.w = to_tf32(v.w);
        *(float4*)(aob + (size_t)(q0 + m) * 512 + c4) = v;
    }
}

// ==================== launch ================================================
extern "C" void kernel_launch(void* const* d_in, const int* in_sizes, int n_in,
                              void* d_out, int out_size)
{
    const float* x     = (const float*)d_in[0];
    const float* gamma = (const float*)d_in[1];
    const float* beta  = (const float*)d_in[2];
    const float* wq    = (const float*)d_in[3];
    const float* bq    = (const float*)d_in[4];
    const float* wk    = (const float*)d_in[5];
    const float* bk    = (const float*)d_in[6];
    const float* wv    = (const float*)d_in[7];
    const float* bv    = (const float*)d_in[8];
    const float* wp    = (const float*)d_in[9];
    const float* bp    = (const float*)d_in[10];
    float* out = (float*)d_out;

    float *stats, *hnT, *W, *q, *k, *v, *ao;
    cudaGetSymbolAddress((void**)&stats, g_stats);
    cudaGetSymbolAddress((void**)&hnT, g_hnT);
    cudaGetSymbolAddress((void**)&W,   g_w);
    cudaGetSymbolAddress((void**)&q,   g_q);
    cudaGetSymbolAddress((void**)&k,   g_k);
    cudaGetSymbolAddress((void**)&v,   g_v);
    cudaGetSymbolAddress((void**)&ao,  g_ao);

    cudaFuncSetAttribute(gemm_tf<0>, cudaFuncAttributeMaxDynamicSharedMemorySize, SMEM_GEMM);
    cudaFuncSetAttribute(gemm_tf<1>, cudaFuncAttributeMaxDynamicSharedMemorySize, SMEM_GEMM);
    cudaFuncSetAttribute(gemm_tf<4>, cudaFuncAttributeMaxDynamicSharedMemorySize, SMEM_GEMM);
    cudaFuncSetAttribute(flash_kernel, cudaFuncAttributeMaxDynamicSharedMemorySize, SMEM_FLASH);

    gn_stats<<<BATCH * NGRP, 256>>>(x, stats);
    t_norm_kernel<<<dim3(32, 16, BATCH), dim3(32, 8)>>>(x, stats, gamma, beta, hnT);
    wconv_kernel<<<dim3(1024, 4), 256>>>(wq, wk, wv, wp, W);

    const long long HNB = (long long)HWSZ * CCH;     // 524288
    const long long WS  = (long long)CCH * CCH;      // 262144

    gemm_tf<0><<<dim3(4, 8, BATCH), 256, SMEM_GEMM>>>(
        hnT, HNB, W + 0 * WS, 0, CCH, bq, nullptr, q);
    gemm_tf<0><<<dim3(4, 8, BATCH), 256, SMEM_GEMM>>>(
        hnT, HNB, W + 1 * WS, 0, CCH, bk, nullptr, k);
    gemm_tf<1><<<dim3(8, 4, BATCH), 256, SMEM_GEMM>>>(
        W + 2 * WS, 0, hnT, HNB, CCH, bv, nullptr, v);
    flash_kernel<<<dim3(8, 64), 512, SMEM_FLASH>>>(q, k, v, ao);
    gemm_tf<4><<<dim3(4, 8, BATCH), 256, SMEM_GEMM>>>(
        ao, HNB, W + 3 * WS, 0, CCH, bp, x, out);
}